// round 1
// baseline (speedup 1.0000x reference)
#include <cuda_runtime.h>
#include <math.h>

// ---------------- problem constants ----------------
#define Dm   768
#define Hh   12
#define DHd  64
#define BLKS 64
#define NB   64          // blocks per sequence (S/BLK)
#define SEQ  4096
#define BB   2
#define NTOK (BB*SEQ)    // 8192
#define RR   3
#define FF   3072

// ---------------- scratch (device globals; no allocation) ----------------
__device__ float g_x  [NTOK*Dm];
__device__ float g_q  [NTOK*Dm];
__device__ float g_k  [NTOK*Dm];
__device__ float g_v  [NTOK*Dm];
__device__ float g_ctx[NTOK*Dm];
__device__ float g_tmp[NTOK*Dm];
__device__ float g_ffn[NTOK*FF];

// ---------------- helpers ----------------
__device__ __forceinline__ float gelu_tanh(float x) {
    float x3 = x * x * x;
    return 0.5f * x * (1.f + tanhf(0.7978845608028654f * (x + 0.044715f * x3)));
}

// block-wide sum for 256 threads
__device__ __forceinline__ float blk_sum256(float v) {
    __shared__ float red[32];
    int lane = threadIdx.x & 31;
    int wid  = threadIdx.x >> 5;
    #pragma unroll
    for (int o = 16; o > 0; o >>= 1) v += __shfl_xor_sync(0xffffffffu, v, o);
    if (lane == 0) red[wid] = v;
    __syncthreads();
    if (wid == 0) {
        v = (lane < 8) ? red[lane] : 0.f;
        #pragma unroll
        for (int o = 4; o > 0; o >>= 1) v += __shfl_xor_sync(0xffffffffu, v, o);
        if (lane == 0) red[0] = v;
    }
    __syncthreads();
    float r = red[0];
    __syncthreads();
    return r;
}

// ---------------- embedding + LN ----------------
__global__ void __launch_bounds__(256) embed_ln_kernel(
    const int* __restrict__ ids, const float* __restrict__ tok,
    const float* __restrict__ pos, const float* __restrict__ g,
    const float* __restrict__ b, float* __restrict__ x)
{
    int t  = blockIdx.x;            // token 0..NTOK-1
    int s  = t & (SEQ - 1);
    int id = ids[t];
    float val[3];
    #pragma unroll
    for (int j = 0; j < 3; j++) {
        int i = threadIdx.x + j * 256;
        val[j] = tok[(size_t)id * Dm + i] + pos[(size_t)s * Dm + i];
    }
    float mean = blk_sum256(val[0] + val[1] + val[2]) * (1.f / 768.f);
    float sq = 0.f;
    #pragma unroll
    for (int j = 0; j < 3; j++) { float d = val[j] - mean; sq += d * d; }
    float var = blk_sum256(sq) * (1.f / 768.f);
    float rstd = rsqrtf(var + 1e-12f);
    #pragma unroll
    for (int j = 0; j < 3; j++) {
        int i = threadIdx.x + j * 256;
        x[(size_t)t * Dm + i] = (val[j] - mean) * rstd * g[i] + b[i];
    }
}

// ---------------- residual add + LN (in place into x) ----------------
__global__ void __launch_bounds__(256) add_ln_kernel(
    float* __restrict__ x, const float* __restrict__ y,
    const float* __restrict__ g, const float* __restrict__ b)
{
    size_t t = blockIdx.x;
    float* xp = x + t * Dm;
    const float* yp = y + t * Dm;
    float val[3];
    #pragma unroll
    for (int j = 0; j < 3; j++) {
        int i = threadIdx.x + j * 256;
        val[j] = xp[i] + yp[i];
    }
    float mean = blk_sum256(val[0] + val[1] + val[2]) * (1.f / 768.f);
    float sq = 0.f;
    #pragma unroll
    for (int j = 0; j < 3; j++) { float d = val[j] - mean; sq += d * d; }
    float var = blk_sum256(sq) * (1.f / 768.f);
    float rstd = rsqrtf(var + 1e-12f);
    #pragma unroll
    for (int j = 0; j < 3; j++) {
        int i = threadIdx.x + j * 256;
        xp[i] = (val[j] - mean) * rstd * g[i] + b[i];
    }
}

// ---------------- SGEMM: C[M,N] = A[M,K] @ B[K,N] + bias (opt GELU) ----------------
// 128x128 tile, BK=8, 256 threads, 8x8 microtile.
template<int GELU>
__global__ void __launch_bounds__(256) sgemm_kernel(
    const float* __restrict__ A, const float* __restrict__ Bw,
    const float* __restrict__ bias, float* __restrict__ C,
    int M, int N, int K)
{
    __shared__ float As[8][128];
    __shared__ float Bs[8][128];
    int tid = threadIdx.x;
    int m0 = blockIdx.y * 128, n0 = blockIdx.x * 128;
    int ty = tid >> 4, tx = tid & 15;
    int arow = tid >> 1, acol = (tid & 1) * 4;
    int brow = tid >> 5, bcol = (tid & 31) * 4;
    const float* Ap = A + (size_t)(m0 + arow) * K + acol;
    const float* Bp = Bw + (size_t)brow * N + n0 + bcol;
    float c[8][8];
    #pragma unroll
    for (int i = 0; i < 8; i++)
        #pragma unroll
        for (int j = 0; j < 8; j++) c[i][j] = 0.f;

    for (int k0 = 0; k0 < K; k0 += 8) {
        float4 av = *(const float4*)(Ap + k0);
        float4 bv = *(const float4*)(Bp + (size_t)k0 * N);
        __syncthreads();
        As[acol + 0][arow] = av.x;
        As[acol + 1][arow] = av.y;
        As[acol + 2][arow] = av.z;
        As[acol + 3][arow] = av.w;
        *(float4*)&Bs[brow][bcol] = bv;
        __syncthreads();
        #pragma unroll
        for (int kk = 0; kk < 8; kk++) {
            float a[8], bb2[8];
            *(float4*)&a[0]   = *(const float4*)&As[kk][ty * 8];
            *(float4*)&a[4]   = *(const float4*)&As[kk][ty * 8 + 4];
            *(float4*)&bb2[0] = *(const float4*)&Bs[kk][tx * 8];
            *(float4*)&bb2[4] = *(const float4*)&Bs[kk][tx * 8 + 4];
            #pragma unroll
            for (int i = 0; i < 8; i++)
                #pragma unroll
                for (int j = 0; j < 8; j++)
                    c[i][j] = fmaf(a[i], bb2[j], c[i][j]);
        }
    }
    #pragma unroll
    for (int jj = 0; jj < 2; jj++) {
        float4 bi = *(const float4*)(bias + n0 + tx * 8 + jj * 4);
        #pragma unroll
        for (int i = 0; i < 8; i++) {
            float4 r;
            r.x = c[i][jj * 4 + 0] + bi.x;
            r.y = c[i][jj * 4 + 1] + bi.y;
            r.z = c[i][jj * 4 + 2] + bi.z;
            r.w = c[i][jj * 4 + 3] + bi.w;
            if (GELU) {
                r.x = gelu_tanh(r.x); r.y = gelu_tanh(r.y);
                r.z = gelu_tanh(r.z); r.w = gelu_tanh(r.w);
            }
            *(float4*)(C + (size_t)(m0 + ty * 8 + i) * N + n0 + tx * 8 + jj * 4) = r;
        }
    }
}

// ---------------- BigBird sparse/dense attention ----------------
// grid (NB, H, B), 256 threads. 4 threads per query (d split in 4x16).
// Online softmax over gathered key blocks (incl. duplicates, matching ref);
// query blocks 0 and NB-1 attend to ALL key blocks (dense rows).
__global__ void __launch_bounds__(256) attn_kernel(
    const float* __restrict__ q, const float* __restrict__ k,
    const float* __restrict__ v, const int* __restrict__ rb,
    float* __restrict__ out)
{
    __shared__ float kv[BLKS * DHd];   // k tile, then reused for v tile
    __shared__ float sc[BLKS * 65];    // scores [query][key], padded stride
    int b = blockIdx.z, h = blockIdx.y, qb = blockIdx.x;
    int tid = threadIdx.x;
    int qi = tid >> 2, dq = tid & 3;
    size_t qoff = ((size_t)(b * SEQ + qb * BLKS + qi)) * Dm + h * DHd + dq * 16;
    float4 qr[4];
    {
        const float4* qp = (const float4*)(q + qoff);
        #pragma unroll
        for (int t = 0; t < 4; t++) qr[t] = qp[t];
    }
    float m = -1e30f, l = 0.f;
    float4 acc[4];
    #pragma unroll
    for (int t = 0; t < 4; t++) acc[t] = make_float4(0.f, 0.f, 0.f, 0.f);

    bool dense = (qb == 0) || (qb == NB - 1);
    int nkb = dense ? NB : 8;
    int blist[8];
    if (!dense) {
        blist[0] = 0; blist[1] = qb - 1; blist[2] = qb; blist[3] = qb + 1;
        blist[4] = NB - 1;
        const int* rp = rb + (h * NB + qb) * RR;
        blist[5] = rp[0]; blist[6] = rp[1]; blist[7] = rp[2];
    }
    int lr = tid >> 2, lc = (tid & 3) * 4;   // loader: row, float4-col base
    const float scale = 0.125f;              // 1/sqrt(64)

    for (int jb = 0; jb < nkb; jb++) {
        int kb = dense ? jb : blist[jb];
        size_t koff = ((size_t)(b * SEQ + kb * BLKS + lr)) * Dm + h * DHd;
        __syncthreads();   // protect previous v/sc reads
        {
            const float4* src = (const float4*)(k + koff);
            float4* dst = (float4*)(kv + lr * DHd);
            #pragma unroll
            for (int t = 0; t < 4; t++) dst[lc + t] = src[lc + t];
        }
        __syncthreads();
        // scores: each group of 4 lanes computes one (query,key) dot
        for (int kk = 0; kk < BLKS; kk++) {
            const float4* kr = (const float4*)(kv + kk * DHd) + dq * 4;
            float s = 0.f;
            #pragma unroll
            for (int t = 0; t < 4; t++) {
                float4 k4 = kr[t];
                s += qr[t].x * k4.x + qr[t].y * k4.y + qr[t].z * k4.z + qr[t].w * k4.w;
            }
            s += __shfl_xor_sync(0xffffffffu, s, 1);
            s += __shfl_xor_sync(0xffffffffu, s, 2);
            if (dq == 0) sc[qi * 65 + kk] = s * scale;
        }
        __syncthreads();   // scores visible; k tile free
        {
            const float4* src = (const float4*)(v + koff);
            float4* dst = (float4*)(kv + lr * DHd);
            #pragma unroll
            for (int t = 0; t < 4; t++) dst[lc + t] = src[lc + t];
        }
        __syncthreads();   // v tile ready
        float bm = -1e30f;
        #pragma unroll 8
        for (int kk = 0; kk < BLKS; kk++) bm = fmaxf(bm, sc[qi * 65 + kk]);
        float mn = fmaxf(m, bm);
        float corr = __expf(m - mn);
        l *= corr;
        #pragma unroll
        for (int t = 0; t < 4; t++) {
            acc[t].x *= corr; acc[t].y *= corr; acc[t].z *= corr; acc[t].w *= corr;
        }
        for (int kk = 0; kk < BLKS; kk++) {
            float p = __expf(sc[qi * 65 + kk] - mn);
            l += p;
            const float4* vr = (const float4*)(kv + kk * DHd) + dq * 4;
            #pragma unroll
            for (int t = 0; t < 4; t++) {
                float4 vv = vr[t];
                acc[t].x = fmaf(p, vv.x, acc[t].x);
                acc[t].y = fmaf(p, vv.y, acc[t].y);
                acc[t].z = fmaf(p, vv.z, acc[t].z);
                acc[t].w = fmaf(p, vv.w, acc[t].w);
            }
        }
        m = mn;
    }
    float inv = 1.f / l;
    float4* op = (float4*)(out + qoff);
    #pragma unroll
    for (int t = 0; t < 4; t++) {
        float4 r;
        r.x = acc[t].x * inv; r.y = acc[t].y * inv;
        r.z = acc[t].z * inv; r.w = acc[t].w * inv;
        op[t] = r;
    }
}

// ---------------- mean pool + linear head ----------------
__global__ void __launch_bounds__(256) pool_fc_kernel(
    const float* __restrict__ x, const float* __restrict__ w,
    const float* __restrict__ fb, float* __restrict__ out)
{
    int b = blockIdx.x;
    __shared__ float ws[Dm];
    for (int i = threadIdx.x; i < Dm; i += 256) ws[i] = w[i];
    __syncthreads();
    const float* xb = x + (size_t)b * SEQ * Dm;
    float acc = 0.f;
    for (int i = threadIdx.x; i < SEQ * Dm; i += 256)
        acc += xb[i] * ws[i % Dm];
    float tot = blk_sum256(acc);
    if (threadIdx.x == 0) out[b] = tot * (1.f / (float)SEQ) + fb[0];
}

// ---------------- driver ----------------
extern "C" void kernel_launch(void* const* d_in, const int* in_sizes, int n_in,
                              void* d_out, int out_size)
{
    const int*   ids     = (const int*)  d_in[0];
    const int*   rb      = (const int*)  d_in[1];
    const float* emb_tok = (const float*)d_in[2];
    const float* emb_pos = (const float*)d_in[3];
    const float* lng     = (const float*)d_in[4];
    const float* lnb     = (const float*)d_in[5];
    const float* Wq = (const float*)d_in[6];  const float* bq = (const float*)d_in[7];
    const float* Wk = (const float*)d_in[8];  const float* bk = (const float*)d_in[9];
    const float* Wv = (const float*)d_in[10]; const float* bv = (const float*)d_in[11];
    const float* Wo = (const float*)d_in[12]; const float* bo = (const float*)d_in[13];
    const float* ln1g = (const float*)d_in[14]; const float* ln1b = (const float*)d_in[15];
    const float* W1 = (const float*)d_in[16]; const float* b1 = (const float*)d_in[17];
    const float* W2 = (const float*)d_in[18]; const float* b2 = (const float*)d_in[19];
    const float* ln2g = (const float*)d_in[20]; const float* ln2b = (const float*)d_in[21];
    const float* fcw = (const float*)d_in[22]; const float* fcb = (const float*)d_in[23];

    float *x, *q, *k, *v, *ctx, *tmp, *ffn;
    cudaGetSymbolAddress((void**)&x,   g_x);
    cudaGetSymbolAddress((void**)&q,   g_q);
    cudaGetSymbolAddress((void**)&k,   g_k);
    cudaGetSymbolAddress((void**)&v,   g_v);
    cudaGetSymbolAddress((void**)&ctx, g_ctx);
    cudaGetSymbolAddress((void**)&tmp, g_tmp);
    cudaGetSymbolAddress((void**)&ffn, g_ffn);

    embed_ln_kernel<<<NTOK, 256>>>(ids, emb_tok, emb_pos, lng, lnb, x);

    dim3 gN(Dm / 128, NTOK / 128);   // N=768 GEMMs
    dim3 gF(FF / 128, NTOK / 128);   // N=3072 GEMM
    dim3 gAtt(NB, Hh, BB);

    for (int l = 0; l < 2; l++) {
        const float* wq = Wq + (size_t)l * Dm * Dm;
        const float* wk = Wk + (size_t)l * Dm * Dm;
        const float* wv = Wv + (size_t)l * Dm * Dm;
        const float* wo = Wo + (size_t)l * Dm * Dm;
        sgemm_kernel<0><<<gN, 256>>>(x, wq, bq + l * Dm, q, NTOK, Dm, Dm);
        sgemm_kernel<0><<<gN, 256>>>(x, wk, bk + l * Dm, k, NTOK, Dm, Dm);
        sgemm_kernel<0><<<gN, 256>>>(x, wv, bv + l * Dm, v, NTOK, Dm, Dm);
        attn_kernel<<<gAtt, 256>>>(q, k, v, rb, ctx);
        sgemm_kernel<0><<<gN, 256>>>(ctx, wo, bo + l * Dm, tmp, NTOK, Dm, Dm);
        add_ln_kernel<<<NTOK, 256>>>(x, tmp, ln1g + l * Dm, ln1b + l * Dm);
        sgemm_kernel<1><<<gF, 256>>>(x, W1 + (size_t)l * Dm * FF, b1 + l * FF, ffn,
                                     NTOK, FF, Dm);
        sgemm_kernel<0><<<gN, 256>>>(ffn, W2 + (size_t)l * FF * Dm, b2 + l * Dm, tmp,
                                     NTOK, Dm, FF);
        add_ln_kernel<<<NTOK, 256>>>(x, tmp, ln2g + l * Dm, ln2b + l * Dm);
    }

    pool_fc_kernel<<<BB, 256>>>(x, fcw, fcb, (float*)d_out);
}

// round 3
// speedup vs baseline: 1.3059x; 1.3059x over previous
#include <cuda_runtime.h>
#include <cuda_bf16.h>
#include <math.h>
#include <stdint.h>

// ---------------- problem constants ----------------
#define Dm   768
#define Hh   12
#define DHd  64
#define BLKS 64
#define NB   64
#define SEQ  4096
#define BB   2
#define NTOK (BB*SEQ)
#define RR   3
#define FF   3072

#define WSZ   589824            // 768*768
#define W1SZ  2359296           // 768*3072
#define OFFL  (4*WSZ + 2*W1SZ)  // per-layer split-weight stride

// ---------------- scratch (device globals) ----------------
__device__ float g_x  [NTOK*Dm];
__device__ float g_q  [NTOK*Dm];
__device__ float g_k  [NTOK*Dm];
__device__ float g_v  [NTOK*Dm];
__device__ float g_ctx[NTOK*Dm];
__device__ float g_tmp[NTOK*Dm];
__device__ float g_ffn[NTOK*FF];
__device__ __nv_bfloat16 g_wh[2*OFFL];
__device__ __nv_bfloat16 g_wl[2*OFFL];
__device__ float g_part[64];

// ---------------- small helpers ----------------
__device__ __forceinline__ float gelu_tanh(float x) {
    float x3 = x * x * x;
    return 0.5f * x * (1.f + tanhf(0.7978845608028654f * (x + 0.044715f * x3)));
}

__device__ __forceinline__ float blk_sum256(float v) {
    __shared__ float red[32];
    int lane = threadIdx.x & 31, wid = threadIdx.x >> 5;
    #pragma unroll
    for (int o = 16; o > 0; o >>= 1) v += __shfl_xor_sync(0xffffffffu, v, o);
    if (lane == 0) red[wid] = v;
    __syncthreads();
    if (wid == 0) {
        v = (lane < 8) ? red[lane] : 0.f;
        #pragma unroll
        for (int o = 4; o > 0; o >>= 1) v += __shfl_xor_sync(0xffffffffu, v, o);
        if (lane == 0) red[0] = v;
    }
    __syncthreads();
    float r = red[0];
    __syncthreads();
    return r;
}

__device__ __forceinline__ uint32_t s2u(const void* p) {
    uint32_t a;
    asm("{ .reg .u64 t; cvta.to.shared.u64 t, %1; cvt.u32.u64 %0, t; }" : "=r"(a) : "l"(p));
    return a;
}

#define LDSM4(r, a) \
    asm volatile("ldmatrix.sync.aligned.m8n8.x4.shared.b16 {%0,%1,%2,%3}, [%4];" \
        : "=r"((r)[0]), "=r"((r)[1]), "=r"((r)[2]), "=r"((r)[3]) : "r"(a))
#define LDSM2(r0, r1, a) \
    asm volatile("ldmatrix.sync.aligned.m8n8.x2.shared.b16 {%0,%1}, [%2];" \
        : "=r"(r0), "=r"(r1) : "r"(a))

__device__ __forceinline__ void mma16816(float* c, const uint32_t* a,
                                         uint32_t b0, uint32_t b1) {
    asm volatile(
        "mma.sync.aligned.m16n8k16.row.col.f32.bf16.bf16.f32 "
        "{%0,%1,%2,%3}, {%4,%5,%6,%7}, {%8,%9}, {%0,%1,%2,%3};"
        : "+f"(c[0]), "+f"(c[1]), "+f"(c[2]), "+f"(c[3])
        : "r"(a[0]), "r"(a[1]), "r"(a[2]), "r"(a[3]), "r"(b0), "r"(b1));
}

__device__ __forceinline__ void split2(float a, float b, uint32_t& hi, uint32_t& lo) {
    __nv_bfloat16 ha = __float2bfloat16_rn(a);
    __nv_bfloat16 hb = __float2bfloat16_rn(b);
    __nv_bfloat16 la = __float2bfloat16_rn(a - __bfloat162float(ha));
    __nv_bfloat16 lb = __float2bfloat16_rn(b - __bfloat162float(hb));
    hi = (uint32_t)__bfloat16_as_ushort(ha) | ((uint32_t)__bfloat16_as_ushort(hb) << 16);
    lo = (uint32_t)__bfloat16_as_ushort(la) | ((uint32_t)__bfloat16_as_ushort(lb) << 16);
}

// ---------------- weight transpose + bf16 hi/lo split ----------------
// W: [K,N] row-major fp32  ->  hi/lo: [N,K] bf16
__global__ void __launch_bounds__(256) wsplit_kernel(
    const float* __restrict__ W, __nv_bfloat16* __restrict__ hi,
    __nv_bfloat16* __restrict__ lo, int K, int N)
{
    __shared__ float t[32][33];
    int n0 = blockIdx.x * 32, k0 = blockIdx.y * 32;
    int tx = threadIdx.x & 31, ty = threadIdx.x >> 5;
    #pragma unroll
    for (int j = 0; j < 4; j++)
        t[ty + j * 8][tx] = W[(size_t)(k0 + ty + j * 8) * N + n0 + tx];
    __syncthreads();
    #pragma unroll
    for (int j = 0; j < 4; j++) {
        int n = n0 + ty + j * 8, k = k0 + tx;
        float v = t[tx][ty + j * 8];
        __nv_bfloat16 h = __float2bfloat16_rn(v);
        hi[(size_t)n * K + k] = h;
        lo[(size_t)n * K + k] = __float2bfloat16_rn(v - __bfloat162float(h));
    }
}

// ---------------- warp-MMA GEMM: C = A @ W + bias (opt GELU) ----------------
// A fp32 [M,K]; Bhi/Blo bf16 [N,K]; C fp32 [M,N].
// 128x128 CTA, BK=32, double-buffered, compensated bf16 (3 HMMA terms).
#define RS_B   80                 // smem row stride bytes (bank-safe padding)
#define TILE_B (128*RS_B)         // 10240
#define STG_B  (4*TILE_B)         // 40960 per stage

template<int GELU>
__global__ void __launch_bounds__(256) gemm_mma(
    const float* __restrict__ A, const __nv_bfloat16* __restrict__ Bhi,
    const __nv_bfloat16* __restrict__ Blo, const float* __restrict__ bias,
    float* __restrict__ C, int M, int N, int K)
{
    extern __shared__ char sm[];
    uint32_t sbase = s2u(sm);
    int tid = threadIdx.x, lane = tid & 31, wid = tid >> 5;
    int m0 = blockIdx.y * 128, n0 = blockIdx.x * 128;
    int wm = (wid & 3) * 32, wn = (wid >> 2) * 64;

    // loader: thread -> row (tid&127), k-half (tid>>7)
    int lr = tid & 127, lh = tid >> 7;
    const float* ap = A + (size_t)(m0 + lr) * K + lh * 16;
    const __nv_bfloat16* bhp = Bhi + (size_t)(n0 + lr) * K + lh * 16;
    const __nv_bfloat16* blp = Blo + (size_t)(n0 + lr) * K + lh * 16;
    uint32_t woff = (uint32_t)lr * RS_B + (uint32_t)lh * 32;

    float acc[2][8][4];
    #pragma unroll
    for (int i = 0; i < 2; i++)
        #pragma unroll
        for (int j = 0; j < 8; j++)
            #pragma unroll
            for (int t = 0; t < 4; t++) acc[i][j][t] = 0.f;

    int chunks = K >> 5;
    float4 a4[4]; uint4 bh4[2], bl4[2];

    // ---- prologue: load chunk 0 ----
    {
        const float4* s = (const float4*)ap;
        a4[0] = s[0]; a4[1] = s[1]; a4[2] = s[2]; a4[3] = s[3];
        const uint4* p1 = (const uint4*)bhp;
        bh4[0] = p1[0]; bh4[1] = p1[1];
        const uint4* p2 = (const uint4*)blp;
        bl4[0] = p2[0]; bl4[1] = p2[1];
    }
    // store chunk 0 into stage 0
    {
        char* st = sm;
        uint32_t hw[8], lw[8];
        #pragma unroll
        for (int j = 0; j < 4; j++) {
            split2(a4[j].x, a4[j].y, hw[2 * j],     lw[2 * j]);
            split2(a4[j].z, a4[j].w, hw[2 * j + 1], lw[2 * j + 1]);
        }
        *(uint4*)(st + woff)              = make_uint4(hw[0], hw[1], hw[2], hw[3]);
        *(uint4*)(st + woff + 16)         = make_uint4(hw[4], hw[5], hw[6], hw[7]);
        *(uint4*)(st + TILE_B + woff)     = make_uint4(lw[0], lw[1], lw[2], lw[3]);
        *(uint4*)(st + TILE_B + woff + 16)= make_uint4(lw[4], lw[5], lw[6], lw[7]);
        *(uint4*)(st + 2*TILE_B + woff)      = bh4[0];
        *(uint4*)(st + 2*TILE_B + woff + 16) = bh4[1];
        *(uint4*)(st + 3*TILE_B + woff)      = bl4[0];
        *(uint4*)(st + 3*TILE_B + woff + 16) = bl4[1];
    }
    __syncthreads();

    int r16 = lane & 15, c16 = lane >> 4;
    int r8  = lane & 7,  c8  = (lane >> 3) & 1;

    for (int c = 0; c < chunks; c++) {
        // prefetch next chunk (global -> regs)
        if (c + 1 < chunks) {
            const float4* s = (const float4*)(ap + (size_t)(c + 1) * 32);
            a4[0] = s[0]; a4[1] = s[1]; a4[2] = s[2]; a4[3] = s[3];
            const uint4* p1 = (const uint4*)(bhp + (size_t)(c + 1) * 32);
            bh4[0] = p1[0]; bh4[1] = p1[1];
            const uint4* p2 = (const uint4*)(blp + (size_t)(c + 1) * 32);
            bl4[0] = p2[0]; bl4[1] = p2[1];
        }
        // compute on stage c&1
        {
            uint32_t base = sbase + (c & 1) * STG_B;
            #pragma unroll
            for (int ks = 0; ks < 2; ks++) {
                uint32_t ah[2][4], al[2][4];
                #pragma unroll
                for (int mi = 0; mi < 2; mi++) {
                    uint32_t rel = (uint32_t)(wm + mi * 16 + r16) * RS_B
                                 + ks * 32 + c16 * 16;
                    LDSM4(ah[mi], base + rel);
                    LDSM4(al[mi], base + TILE_B + rel);
                }
                #pragma unroll
                for (int ni = 0; ni < 8; ni++) {
                    uint32_t rel = (uint32_t)(wn + ni * 8 + r8) * RS_B
                                 + ks * 32 + c8 * 16;
                    uint32_t bh0, bh1, bl0, bl1;
                    LDSM2(bh0, bh1, base + 2 * TILE_B + rel);
                    LDSM2(bl0, bl1, base + 3 * TILE_B + rel);
                    #pragma unroll
                    for (int mi = 0; mi < 2; mi++) {
                        mma16816(acc[mi][ni], ah[mi], bh0, bh1);
                        mma16816(acc[mi][ni], ah[mi], bl0, bl1);
                        mma16816(acc[mi][ni], al[mi], bh0, bh1);
                    }
                }
            }
        }
        // store next chunk into the other stage
        if (c + 1 < chunks) {
            char* st = sm + ((c + 1) & 1) * STG_B;
            uint32_t hw[8], lw[8];
            #pragma unroll
            for (int j = 0; j < 4; j++) {
                split2(a4[j].x, a4[j].y, hw[2 * j],     lw[2 * j]);
                split2(a4[j].z, a4[j].w, hw[2 * j + 1], lw[2 * j + 1]);
            }
            *(uint4*)(st + woff)              = make_uint4(hw[0], hw[1], hw[2], hw[3]);
            *(uint4*)(st + woff + 16)         = make_uint4(hw[4], hw[5], hw[6], hw[7]);
            *(uint4*)(st + TILE_B + woff)     = make_uint4(lw[0], lw[1], lw[2], lw[3]);
            *(uint4*)(st + TILE_B + woff + 16)= make_uint4(lw[4], lw[5], lw[6], lw[7]);
            *(uint4*)(st + 2*TILE_B + woff)      = bh4[0];
            *(uint4*)(st + 2*TILE_B + woff + 16) = bh4[1];
            *(uint4*)(st + 3*TILE_B + woff)      = bl4[0];
            *(uint4*)(st + 3*TILE_B + woff + 16) = bl4[1];
        }
        __syncthreads();
    }

    // ---- epilogue ----
    int g = lane >> 2, t4 = lane & 3;
    #pragma unroll
    for (int mi = 0; mi < 2; mi++) {
        int row0 = m0 + wm + mi * 16 + g;
        #pragma unroll
        for (int ni = 0; ni < 8; ni++) {
            int col = n0 + wn + ni * 8 + 2 * t4;
            float2 bi = *(const float2*)(bias + col);
            float2 o0, o1;
            o0.x = acc[mi][ni][0] + bi.x;
            o0.y = acc[mi][ni][1] + bi.y;
            o1.x = acc[mi][ni][2] + bi.x;
            o1.y = acc[mi][ni][3] + bi.y;
            if (GELU) {
                o0.x = gelu_tanh(o0.x); o0.y = gelu_tanh(o0.y);
                o1.x = gelu_tanh(o1.x); o1.y = gelu_tanh(o1.y);
            }
            *(float2*)(C + (size_t)row0 * N + col)       = o0;
            *(float2*)(C + (size_t)(row0 + 8) * N + col) = o1;
        }
    }
}

// ---------------- embedding + LN ----------------
__global__ void __launch_bounds__(256) embed_ln_kernel(
    const int* __restrict__ ids, const float* __restrict__ tok,
    const float* __restrict__ pos, const float* __restrict__ g,
    const float* __restrict__ b, float* __restrict__ x)
{
    int t = blockIdx.x, s = t & (SEQ - 1), id = ids[t];
    float val[3];
    #pragma unroll
    for (int j = 0; j < 3; j++) {
        int i = threadIdx.x + j * 256;
        val[j] = tok[(size_t)id * Dm + i] + pos[(size_t)s * Dm + i];
    }
    float mean = blk_sum256(val[0] + val[1] + val[2]) * (1.f / 768.f);
    float sq = 0.f;
    #pragma unroll
    for (int j = 0; j < 3; j++) { float d = val[j] - mean; sq += d * d; }
    float rstd = rsqrtf(blk_sum256(sq) * (1.f / 768.f) + 1e-12f);
    #pragma unroll
    for (int j = 0; j < 3; j++) {
        int i = threadIdx.x + j * 256;
        x[(size_t)t * Dm + i] = (val[j] - mean) * rstd * g[i] + b[i];
    }
}

// ---------------- residual add + LN ----------------
__global__ void __launch_bounds__(256) add_ln_kernel(
    float* __restrict__ x, const float* __restrict__ y,
    const float* __restrict__ g, const float* __restrict__ b)
{
    size_t t = blockIdx.x;
    float* xp = x + t * Dm;
    const float* yp = y + t * Dm;
    float val[3];
    #pragma unroll
    for (int j = 0; j < 3; j++) {
        int i = threadIdx.x + j * 256;
        val[j] = xp[i] + yp[i];
    }
    float mean = blk_sum256(val[0] + val[1] + val[2]) * (1.f / 768.f);
    float sq = 0.f;
    #pragma unroll
    for (int j = 0; j < 3; j++) { float d = val[j] - mean; sq += d * d; }
    float rstd = rsqrtf(blk_sum256(sq) * (1.f / 768.f) + 1e-12f);
    #pragma unroll
    for (int j = 0; j < 3; j++) {
        int i = threadIdx.x + j * 256;
        xp[i] = (val[j] - mean) * rstd * g[i] + b[i];
    }
}

// ---------------- BigBird sparse/dense attention ----------------
__global__ void __launch_bounds__(256) attn_kernel(
    const float* __restrict__ q, const float* __restrict__ k,
    const float* __restrict__ v, const int* __restrict__ rb,
    float* __restrict__ out)
{
    __shared__ float kv[BLKS * DHd];
    __shared__ float sc[BLKS * 65];
    int b = blockIdx.z, h = blockIdx.y, qb = blockIdx.x;
    int tid = threadIdx.x;
    int qi = tid >> 2, dq = tid & 3;
    size_t qoff = ((size_t)(b * SEQ + qb * BLKS + qi)) * Dm + h * DHd + dq * 16;
    float4 qr[4];
    {
        const float4* qp = (const float4*)(q + qoff);
        #pragma unroll
        for (int t = 0; t < 4; t++) qr[t] = qp[t];
    }
    float m = -1e30f, l = 0.f;
    float4 acc[4];
    #pragma unroll
    for (int t = 0; t < 4; t++) acc[t] = make_float4(0.f, 0.f, 0.f, 0.f);

    bool dense = (qb == 0) || (qb == NB - 1);
    int nkb = dense ? NB : 8;
    int blist[8];
    if (!dense) {
        blist[0] = 0; blist[1] = qb - 1; blist[2] = qb; blist[3] = qb + 1;
        blist[4] = NB - 1;
        const int* rp = rb + (h * NB + qb) * RR;
        blist[5] = rp[0]; blist[6] = rp[1]; blist[7] = rp[2];
    }
    int lr = tid >> 2, lc = (tid & 3) * 4;
    const float scale = 0.125f;

    for (int jb = 0; jb < nkb; jb++) {
        int kb = dense ? jb : blist[jb];
        size_t koff = ((size_t)(b * SEQ + kb * BLKS + lr)) * Dm + h * DHd;
        __syncthreads();
        {
            const float4* src = (const float4*)(k + koff);
            float4* dst = (float4*)(kv + lr * DHd);
            #pragma unroll
            for (int t = 0; t < 4; t++) dst[lc + t] = src[lc + t];
        }
        __syncthreads();
        for (int kk = 0; kk < BLKS; kk++) {
            const float4* kr = (const float4*)(kv + kk * DHd) + dq * 4;
            float s = 0.f;
            #pragma unroll
            for (int t = 0; t < 4; t++) {
                float4 k4 = kr[t];
                s += qr[t].x * k4.x + qr[t].y * k4.y + qr[t].z * k4.z + qr[t].w * k4.w;
            }
            s += __shfl_xor_sync(0xffffffffu, s, 1);
            s += __shfl_xor_sync(0xffffffffu, s, 2);
            if (dq == 0) sc[qi * 65 + kk] = s * scale;
        }
        __syncthreads();
        {
            const float4* src = (const float4*)(v + koff);
            float4* dst = (float4*)(kv + lr * DHd);
            #pragma unroll
            for (int t = 0; t < 4; t++) dst[lc + t] = src[lc + t];
        }
        __syncthreads();
        float bm = -1e30f;
        #pragma unroll 8
        for (int kk = 0; kk < BLKS; kk++) bm = fmaxf(bm, sc[qi * 65 + kk]);
        float mn = fmaxf(m, bm);
        float corr = __expf(m - mn);
        l *= corr;
        #pragma unroll
        for (int t = 0; t < 4; t++) {
            acc[t].x *= corr; acc[t].y *= corr; acc[t].z *= corr; acc[t].w *= corr;
        }
        for (int kk = 0; kk < BLKS; kk++) {
            float p = __expf(sc[qi * 65 + kk] - mn);
            l += p;
            const float4* vr = (const float4*)(kv + kk * DHd) + dq * 4;
            #pragma unroll
            for (int t = 0; t < 4; t++) {
                float4 vv = vr[t];
                acc[t].x = fmaf(p, vv.x, acc[t].x);
                acc[t].y = fmaf(p, vv.y, acc[t].y);
                acc[t].z = fmaf(p, vv.z, acc[t].z);
                acc[t].w = fmaf(p, vv.w, acc[t].w);
            }
        }
        m = mn;
    }
    float inv = 1.f / l;
    float4* op = (float4*)(out + qoff);
    #pragma unroll
    for (int t = 0; t < 4; t++) {
        float4 rr;
        rr.x = acc[t].x * inv; rr.y = acc[t].y * inv;
        rr.z = acc[t].z * inv; rr.w = acc[t].w * inv;
        op[t] = rr;
    }
}

// ---------------- mean pool + linear head (two stage) ----------------
__global__ void __launch_bounds__(256) pool1_kernel(
    const float* __restrict__ x, const float* __restrict__ w, float* __restrict__ part)
{
    int b = blockIdx.y, sl = blockIdx.x;
    const float* xb = x + ((size_t)b * SEQ + sl * 128) * Dm;
    __shared__ float ws[Dm];
    for (int i = threadIdx.x; i < Dm; i += 256) ws[i] = w[i];
    __syncthreads();
    float acc = 0.f;
    for (int i = threadIdx.x; i < 128 * Dm; i += 256) acc += xb[i] * ws[i % Dm];
    float t = blk_sum256(acc);
    if (threadIdx.x == 0) part[b * 32 + sl] = t;
}
__global__ void pool2_kernel(const float* __restrict__ part,
                             const float* __restrict__ fb, float* __restrict__ out)
{
    int b = threadIdx.x;
    if (b < BB) {
        float s = 0.f;
        for (int i = 0; i < 32; i++) s += part[b * 32 + i];
        out[b] = s * (1.f / (float)SEQ) + fb[0];
    }
}

// ---------------- driver ----------------
extern "C" void kernel_launch(void* const* d_in, const int* in_sizes, int n_in,
                              void* d_out, int out_size)
{
    const int*   ids     = (const int*)  d_in[0];
    const int*   rb      = (const int*)  d_in[1];
    const float* emb_tok = (const float*)d_in[2];
    const float* emb_pos = (const float*)d_in[3];
    const float* lng     = (const float*)d_in[4];
    const float* lnb     = (const float*)d_in[5];
    const float* Wq = (const float*)d_in[6];  const float* bq = (const float*)d_in[7];
    const float* Wk = (const float*)d_in[8];  const float* bk = (const float*)d_in[9];
    const float* Wv = (const float*)d_in[10]; const float* bv = (const float*)d_in[11];
    const float* Wo = (const float*)d_in[12]; const float* bo = (const float*)d_in[13];
    const float* ln1g = (const float*)d_in[14]; const float* ln1b = (const float*)d_in[15];
    const float* W1 = (const float*)d_in[16]; const float* b1 = (const float*)d_in[17];
    const float* W2 = (const float*)d_in[18]; const float* b2 = (const float*)d_in[19];
    const float* ln2g = (const float*)d_in[20]; const float* ln2b = (const float*)d_in[21];
    const float* fcw = (const float*)d_in[22]; const float* fcb = (const float*)d_in[23];

    float *x, *q, *k, *v, *ctx, *tmp, *ffn, *part;
    __nv_bfloat16 *wh, *wl;
    cudaGetSymbolAddress((void**)&x,   g_x);
    cudaGetSymbolAddress((void**)&q,   g_q);
    cudaGetSymbolAddress((void**)&k,   g_k);
    cudaGetSymbolAddress((void**)&v,   g_v);
    cudaGetSymbolAddress((void**)&ctx, g_ctx);
    cudaGetSymbolAddress((void**)&tmp, g_tmp);
    cudaGetSymbolAddress((void**)&ffn, g_ffn);
    cudaGetSymbolAddress((void**)&wh,  g_wh);
    cudaGetSymbolAddress((void**)&wl,  g_wl);
    cudaGetSymbolAddress((void**)&part, g_part);

    const int SMEM_GEMM = 2 * STG_B;   // 81920
    cudaFuncSetAttribute((const void*)gemm_mma<0>,
                         cudaFuncAttributeMaxDynamicSharedMemorySize, SMEM_GEMM);
    cudaFuncSetAttribute((const void*)gemm_mma<1>,
                         cudaFuncAttributeMaxDynamicSharedMemorySize, SMEM_GEMM);

    // pre-split all weights (transpose + bf16 hi/lo)
    for (int l = 0; l < 2; l++) {
        size_t o = (size_t)l * OFFL;
        wsplit_kernel<<<dim3(Dm / 32, Dm / 32), 256>>>(Wq + (size_t)l * WSZ, wh + o,           wl + o,           Dm, Dm);
        wsplit_kernel<<<dim3(Dm / 32, Dm / 32), 256>>>(Wk + (size_t)l * WSZ, wh + o + WSZ,     wl + o + WSZ,     Dm, Dm);
        wsplit_kernel<<<dim3(Dm / 32, Dm / 32), 256>>>(Wv + (size_t)l * WSZ, wh + o + 2 * WSZ, wl + o + 2 * WSZ, Dm, Dm);
        wsplit_kernel<<<dim3(Dm / 32, Dm / 32), 256>>>(Wo + (size_t)l * WSZ, wh + o + 3 * WSZ, wl + o + 3 * WSZ, Dm, Dm);
        wsplit_kernel<<<dim3(FF / 32, Dm / 32), 256>>>(W1 + (size_t)l * W1SZ, wh + o + 4 * WSZ, wl + o + 4 * WSZ, Dm, FF);
        wsplit_kernel<<<dim3(Dm / 32, FF / 32), 256>>>(W2 + (size_t)l * W1SZ, wh + o + 4 * WSZ + W1SZ, wl + o + 4 * WSZ + W1SZ, FF, Dm);
    }

    embed_ln_kernel<<<NTOK, 256>>>(ids, emb_tok, emb_pos, lng, lnb, x);

    dim3 gN(Dm / 128, NTOK / 128);
    dim3 gF(FF / 128, NTOK / 128);
    dim3 gAtt(NB, Hh, BB);

    for (int l = 0; l < 2; l++) {
        size_t o = (size_t)l * OFFL;
        gemm_mma<0><<<gN, 256, SMEM_GEMM>>>(x,   wh + o,           wl + o,           bq + l * Dm, q,   NTOK, Dm, Dm);
        gemm_mma<0><<<gN, 256, SMEM_GEMM>>>(x,   wh + o + WSZ,     wl + o + WSZ,     bk + l * Dm, k,   NTOK, Dm, Dm);
        gemm_mma<0><<<gN, 256, SMEM_GEMM>>>(x,   wh + o + 2 * WSZ, wl + o + 2 * WSZ, bv + l * Dm, v,   NTOK, Dm, Dm);
        attn_kernel<<<gAtt, 256>>>(q, k, v, rb, ctx);
        gemm_mma<0><<<gN, 256, SMEM_GEMM>>>(ctx, wh + o + 3 * WSZ, wl + o + 3 * WSZ, bo + l * Dm, tmp, NTOK, Dm, Dm);
        add_ln_kernel<<<NTOK, 256>>>(x, tmp, ln1g + l * Dm, ln1b + l * Dm);
        gemm_mma<1><<<gF, 256, SMEM_GEMM>>>(x,   wh + o + 4 * WSZ, wl + o + 4 * WSZ, b1 + l * FF, ffn, NTOK, FF, Dm);
        gemm_mma<0><<<gN, 256, SMEM_GEMM>>>(ffn, wh + o + 4 * WSZ + W1SZ, wl + o + 4 * WSZ + W1SZ, b2 + l * Dm, tmp, NTOK, Dm, FF);
        add_ln_kernel<<<NTOK, 256>>>(x, tmp, ln2g + l * Dm, ln2b + l * Dm);
    }

    pool1_kernel<<<dim3(32, BB), 256>>>(x, fcw, part);
    pool2_kernel<<<1, 32>>>(part, fcb, (float*)d_out);
}

// round 5
// speedup vs baseline: 2.9594x; 2.2663x over previous
#include <cuda_runtime.h>
#include <cuda_bf16.h>
#include <math.h>
#include <stdint.h>

// ---------------- problem constants ----------------
#define Dm   768
#define Hh   12
#define DHd  64
#define BLKS 64
#define NB   64
#define SEQ  4096
#define BB   2
#define NTOK (BB*SEQ)
#define RR   3
#define FF   3072

#define WSZ   589824            // 768*768
#define W1SZ  2359296           // 768*3072
#define OFFL  (4*WSZ + 2*W1SZ)  // per-layer split-weight stride

// ---------------- scratch (device globals) ----------------
__device__ float g_x  [NTOK*Dm];
__device__ float g_q  [NTOK*Dm];
__device__ float g_k  [NTOK*Dm];
__device__ float g_v  [NTOK*Dm];
__device__ float g_ctx[NTOK*Dm];
__device__ float g_tmp[NTOK*Dm];
__device__ float g_ffn[NTOK*FF];
__device__ __nv_bfloat16 g_wh[2*OFFL];
__device__ __nv_bfloat16 g_wl[2*OFFL];
__device__ float g_part[64];

// ---------------- small helpers ----------------
__device__ __forceinline__ float gelu_tanh(float x) {
    float x3 = x * x * x;
    return 0.5f * x * (1.f + tanhf(0.7978845608028654f * (x + 0.044715f * x3)));
}

__device__ __forceinline__ float blk_sum256(float v) {
    __shared__ float red[32];
    int lane = threadIdx.x & 31, wid = threadIdx.x >> 5;
    #pragma unroll
    for (int o = 16; o > 0; o >>= 1) v += __shfl_xor_sync(0xffffffffu, v, o);
    if (lane == 0) red[wid] = v;
    __syncthreads();
    if (wid == 0) {
        v = (lane < 8) ? red[lane] : 0.f;
        #pragma unroll
        for (int o = 4; o > 0; o >>= 1) v += __shfl_xor_sync(0xffffffffu, v, o);
        if (lane == 0) red[0] = v;
    }
    __syncthreads();
    float r = red[0];
    __syncthreads();
    return r;
}

__device__ __forceinline__ uint32_t s2u(const void* p) {
    uint32_t a;
    asm("{ .reg .u64 t; cvta.to.shared.u64 t, %1; cvt.u32.u64 %0, t; }" : "=r"(a) : "l"(p));
    return a;
}

#define LDSM4(r, a) \
    asm volatile("ldmatrix.sync.aligned.m8n8.x4.shared.b16 {%0,%1,%2,%3}, [%4];" \
        : "=r"((r)[0]), "=r"((r)[1]), "=r"((r)[2]), "=r"((r)[3]) : "r"(a))
#define LDSM2(r0, r1, a) \
    asm volatile("ldmatrix.sync.aligned.m8n8.x2.shared.b16 {%0,%1}, [%2];" \
        : "=r"(r0), "=r"(r1) : "r"(a))

__device__ __forceinline__ void mma16816(float* c, const uint32_t* a,
                                         uint32_t b0, uint32_t b1) {
    asm volatile(
        "mma.sync.aligned.m16n8k16.row.col.f32.bf16.bf16.f32 "
        "{%0,%1,%2,%3}, {%4,%5,%6,%7}, {%8,%9}, {%0,%1,%2,%3};"
        : "+f"(c[0]), "+f"(c[1]), "+f"(c[2]), "+f"(c[3])
        : "r"(a[0]), "r"(a[1]), "r"(a[2]), "r"(a[3]), "r"(b0), "r"(b1));
}

__device__ __forceinline__ void split2(float a, float b, uint32_t& hi, uint32_t& lo) {
    __nv_bfloat16 ha = __float2bfloat16_rn(a);
    __nv_bfloat16 hb = __float2bfloat16_rn(b);
    __nv_bfloat16 la = __float2bfloat16_rn(a - __bfloat162float(ha));
    __nv_bfloat16 lb = __float2bfloat16_rn(b - __bfloat162float(hb));
    hi = (uint32_t)__bfloat16_as_ushort(ha) | ((uint32_t)__bfloat16_as_ushort(hb) << 16);
    lo = (uint32_t)__bfloat16_as_ushort(la) | ((uint32_t)__bfloat16_as_ushort(lb) << 16);
}

// ---------------- weight transpose + bf16 hi/lo split ----------------
__global__ void __launch_bounds__(256) wsplit_kernel(
    const float* __restrict__ W, __nv_bfloat16* __restrict__ hi,
    __nv_bfloat16* __restrict__ lo, int K, int N)
{
    __shared__ float t[32][33];
    int n0 = blockIdx.x * 32, k0 = blockIdx.y * 32;
    int tx = threadIdx.x & 31, ty = threadIdx.x >> 5;
    #pragma unroll
    for (int j = 0; j < 4; j++)
        t[ty + j * 8][tx] = W[(size_t)(k0 + ty + j * 8) * N + n0 + tx];
    __syncthreads();
    #pragma unroll
    for (int j = 0; j < 4; j++) {
        int n = n0 + ty + j * 8, k = k0 + tx;
        float v = t[tx][ty + j * 8];
        __nv_bfloat16 h = __float2bfloat16_rn(v);
        hi[(size_t)n * K + k] = h;
        lo[(size_t)n * K + k] = __float2bfloat16_rn(v - __bfloat162float(h));
    }
}

// combined q/k/v split (one launch): z selects source; dst offset z*WSZ.
__global__ void __launch_bounds__(256) wsplit3_kernel(
    const float* __restrict__ Wa, const float* __restrict__ Wb,
    const float* __restrict__ Wc, __nv_bfloat16* __restrict__ hi,
    __nv_bfloat16* __restrict__ lo)
{
    __shared__ float t[32][33];
    int z = blockIdx.z;
    const float* W = (z == 0) ? Wa : (z == 1) ? Wb : Wc;
    __nv_bfloat16* hz = hi + (size_t)z * WSZ;
    __nv_bfloat16* lz = lo + (size_t)z * WSZ;
    int n0 = blockIdx.x * 32, k0 = blockIdx.y * 32;
    int tx = threadIdx.x & 31, ty = threadIdx.x >> 5;
    #pragma unroll
    for (int j = 0; j < 4; j++)
        t[ty + j * 8][tx] = W[(size_t)(k0 + ty + j * 8) * Dm + n0 + tx];
    __syncthreads();
    #pragma unroll
    for (int j = 0; j < 4; j++) {
        int n = n0 + ty + j * 8, k = k0 + tx;
        float v = t[tx][ty + j * 8];
        __nv_bfloat16 h = __float2bfloat16_rn(v);
        hz[(size_t)n * Dm + k] = h;
        lz[(size_t)n * Dm + k] = __float2bfloat16_rn(v - __bfloat162float(h));
    }
}

// ---------------- warp-MMA GEMM (unchanged from R3, verified) ----------------
#define RS_B   80
#define TILE_B (128*RS_B)
#define STG_B  (4*TILE_B)

template<int GELU>
__global__ void __launch_bounds__(256) gemm_mma(
    const float* __restrict__ A, const __nv_bfloat16* __restrict__ Bhi,
    const __nv_bfloat16* __restrict__ Blo, const float* __restrict__ bias,
    float* __restrict__ C, int M, int N, int K)
{
    extern __shared__ char sm[];
    uint32_t sbase = s2u(sm);
    int tid = threadIdx.x, lane = tid & 31, wid = tid >> 5;
    int m0 = blockIdx.y * 128, n0 = blockIdx.x * 128;
    int wm = (wid & 3) * 32, wn = (wid >> 2) * 64;

    int lr = tid & 127, lh = tid >> 7;
    const float* ap = A + (size_t)(m0 + lr) * K + lh * 16;
    const __nv_bfloat16* bhp = Bhi + (size_t)(n0 + lr) * K + lh * 16;
    const __nv_bfloat16* blp = Blo + (size_t)(n0 + lr) * K + lh * 16;
    uint32_t woff = (uint32_t)lr * RS_B + (uint32_t)lh * 32;

    float acc[2][8][4];
    #pragma unroll
    for (int i = 0; i < 2; i++)
        #pragma unroll
        for (int j = 0; j < 8; j++)
            #pragma unroll
            for (int t = 0; t < 4; t++) acc[i][j][t] = 0.f;

    int chunks = K >> 5;
    float4 a4[4]; uint4 bh4[2], bl4[2];

    {
        const float4* s = (const float4*)ap;
        a4[0] = s[0]; a4[1] = s[1]; a4[2] = s[2]; a4[3] = s[3];
        const uint4* p1 = (const uint4*)bhp;
        bh4[0] = p1[0]; bh4[1] = p1[1];
        const uint4* p2 = (const uint4*)blp;
        bl4[0] = p2[0]; bl4[1] = p2[1];
    }
    {
        char* st = sm;
        uint32_t hw[8], lw[8];
        #pragma unroll
        for (int j = 0; j < 4; j++) {
            split2(a4[j].x, a4[j].y, hw[2 * j],     lw[2 * j]);
            split2(a4[j].z, a4[j].w, hw[2 * j + 1], lw[2 * j + 1]);
        }
        *(uint4*)(st + woff)              = make_uint4(hw[0], hw[1], hw[2], hw[3]);
        *(uint4*)(st + woff + 16)         = make_uint4(hw[4], hw[5], hw[6], hw[7]);
        *(uint4*)(st + TILE_B + woff)     = make_uint4(lw[0], lw[1], lw[2], lw[3]);
        *(uint4*)(st + TILE_B + woff + 16)= make_uint4(lw[4], lw[5], lw[6], lw[7]);
        *(uint4*)(st + 2*TILE_B + woff)      = bh4[0];
        *(uint4*)(st + 2*TILE_B + woff + 16) = bh4[1];
        *(uint4*)(st + 3*TILE_B + woff)      = bl4[0];
        *(uint4*)(st + 3*TILE_B + woff + 16) = bl4[1];
    }
    __syncthreads();

    int r16 = lane & 15, c16 = lane >> 4;
    int r8  = lane & 7,  c8  = (lane >> 3) & 1;

    for (int c = 0; c < chunks; c++) {
        if (c + 1 < chunks) {
            const float4* s = (const float4*)(ap + (size_t)(c + 1) * 32);
            a4[0] = s[0]; a4[1] = s[1]; a4[2] = s[2]; a4[3] = s[3];
            const uint4* p1 = (const uint4*)(bhp + (size_t)(c + 1) * 32);
            bh4[0] = p1[0]; bh4[1] = p1[1];
            const uint4* p2 = (const uint4*)(blp + (size_t)(c + 1) * 32);
            bl4[0] = p2[0]; bl4[1] = p2[1];
        }
        {
            uint32_t base = sbase + (c & 1) * STG_B;
            #pragma unroll
            for (int ks = 0; ks < 2; ks++) {
                uint32_t ah[2][4], al[2][4];
                #pragma unroll
                for (int mi = 0; mi < 2; mi++) {
                    uint32_t rel = (uint32_t)(wm + mi * 16 + r16) * RS_B
                                 + ks * 32 + c16 * 16;
                    LDSM4(ah[mi], base + rel);
                    LDSM4(al[mi], base + TILE_B + rel);
                }
                #pragma unroll
                for (int ni = 0; ni < 8; ni++) {
                    uint32_t rel = (uint32_t)(wn + ni * 8 + r8) * RS_B
                                 + ks * 32 + c8 * 16;
                    uint32_t bh0, bh1, bl0, bl1;
                    LDSM2(bh0, bh1, base + 2 * TILE_B + rel);
                    LDSM2(bl0, bl1, base + 3 * TILE_B + rel);
                    #pragma unroll
                    for (int mi = 0; mi < 2; mi++) {
                        mma16816(acc[mi][ni], ah[mi], bh0, bh1);
                        mma16816(acc[mi][ni], ah[mi], bl0, bl1);
                        mma16816(acc[mi][ni], al[mi], bh0, bh1);
                    }
                }
            }
        }
        if (c + 1 < chunks) {
            char* st = sm + ((c + 1) & 1) * STG_B;
            uint32_t hw[8], lw[8];
            #pragma unroll
            for (int j = 0; j < 4; j++) {
                split2(a4[j].x, a4[j].y, hw[2 * j],     lw[2 * j]);
                split2(a4[j].z, a4[j].w, hw[2 * j + 1], lw[2 * j + 1]);
            }
            *(uint4*)(st + woff)              = make_uint4(hw[0], hw[1], hw[2], hw[3]);
            *(uint4*)(st + woff + 16)         = make_uint4(hw[4], hw[5], hw[6], hw[7]);
            *(uint4*)(st + TILE_B + woff)     = make_uint4(lw[0], lw[1], lw[2], lw[3]);
            *(uint4*)(st + TILE_B + woff + 16)= make_uint4(lw[4], lw[5], lw[6], lw[7]);
            *(uint4*)(st + 2*TILE_B + woff)      = bh4[0];
            *(uint4*)(st + 2*TILE_B + woff + 16) = bh4[1];
            *(uint4*)(st + 3*TILE_B + woff)      = bl4[0];
            *(uint4*)(st + 3*TILE_B + woff + 16) = bl4[1];
        }
        __syncthreads();
    }

    int g = lane >> 2, t4 = lane & 3;
    #pragma unroll
    for (int mi = 0; mi < 2; mi++) {
        int row0 = m0 + wm + mi * 16 + g;
        #pragma unroll
        for (int ni = 0; ni < 8; ni++) {
            int col = n0 + wn + ni * 8 + 2 * t4;
            float2 bi = *(const float2*)(bias + col);
            float2 o0, o1;
            o0.x = acc[mi][ni][0] + bi.x;
            o0.y = acc[mi][ni][1] + bi.y;
            o1.x = acc[mi][ni][2] + bi.x;
            o1.y = acc[mi][ni][3] + bi.y;
            if (GELU) {
                o0.x = gelu_tanh(o0.x); o0.y = gelu_tanh(o0.y);
                o1.x = gelu_tanh(o1.x); o1.y = gelu_tanh(o1.y);
            }
            *(float2*)(C + (size_t)row0 * N + col)       = o0;
            *(float2*)(C + (size_t)(row0 + 8) * N + col) = o1;
        }
    }
}

// ---------------- embedding + LN ----------------
__global__ void __launch_bounds__(256) embed_ln_kernel(
    const int* __restrict__ ids, const float* __restrict__ tok,
    const float* __restrict__ pos, const float* __restrict__ g,
    const float* __restrict__ b, float* __restrict__ x)
{
    int t = blockIdx.x, s = t & (SEQ - 1), id = ids[t];
    float val[3];
    #pragma unroll
    for (int j = 0; j < 3; j++) {
        int i = threadIdx.x + j * 256;
        val[j] = tok[(size_t)id * Dm + i] + pos[(size_t)s * Dm + i];
    }
    float mean = blk_sum256(val[0] + val[1] + val[2]) * (1.f / 768.f);
    float sq = 0.f;
    #pragma unroll
    for (int j = 0; j < 3; j++) { float d = val[j] - mean; sq += d * d; }
    float rstd = rsqrtf(blk_sum256(sq) * (1.f / 768.f) + 1e-12f);
    #pragma unroll
    for (int j = 0; j < 3; j++) {
        int i = threadIdx.x + j * 256;
        x[(size_t)t * Dm + i] = (val[j] - mean) * rstd * g[i] + b[i];
    }
}

// ---------------- residual add + LN ----------------
__global__ void __launch_bounds__(256) add_ln_kernel(
    float* __restrict__ x, const float* __restrict__ y,
    const float* __restrict__ g, const float* __restrict__ b)
{
    size_t t = blockIdx.x;
    float* xp = x + t * Dm;
    const float* yp = y + t * Dm;
    float val[3];
    #pragma unroll
    for (int j = 0; j < 3; j++) {
        int i = threadIdx.x + j * 256;
        val[j] = xp[i] + yp[i];
    }
    float mean = blk_sum256(val[0] + val[1] + val[2]) * (1.f / 768.f);
    float sq = 0.f;
    #pragma unroll
    for (int j = 0; j < 3; j++) { float d = val[j] - mean; sq += d * d; }
    float rstd = rsqrtf(blk_sum256(sq) * (1.f / 768.f) + 1e-12f);
    #pragma unroll
    for (int j = 0; j < 3; j++) {
        int i = threadIdx.x + j * 256;
        xp[i] = (val[j] - mean) * rstd * g[i] + b[i];
    }
}

// ---------------- BigBird attention via HMMA (flash-style) ----------------
// CTA = (qb, h, b), 128 threads = 4 warps; warp w owns query rows 16w..16w+15.
// K tiles [key][d] hi/lo; V tiles transposed [d][key] hi/lo; Q staged once
// (pre-scaled by 1/8). 3-term compensated bf16 for both S=QK^T and ctx=P*V.
#define ARS 144                      // smem row stride (64 bf16 = 128B + 16 pad)
#define A_QH 0
#define A_QL 9216
#define A_KH 18432
#define A_KL 27648
#define A_VH 36864
#define A_VL 46080
#define A_SMEM 55296

__global__ void __launch_bounds__(128) attn_mma_kernel(
    const float* __restrict__ q, const float* __restrict__ k,
    const float* __restrict__ v, const int* __restrict__ rb,
    float* __restrict__ out)
{
    extern __shared__ char sb[];
    uint32_t sbase = s2u(sb);
    int b = blockIdx.z, h = blockIdx.y, qb = blockIdx.x;
    int tid = threadIdx.x, lane = tid & 31, w = tid >> 5;

    // ---- stage Q (scaled by 0.125) ----
    {
        int row = tid >> 1, half = tid & 1;
        const float4* src = (const float4*)(q
            + ((size_t)(b * SEQ + qb * BLKS + row)) * Dm + h * DHd + half * 32);
        uint32_t hw[16], lw[16];
        #pragma unroll
        for (int j = 0; j < 8; j++) {
            float4 f = src[j];
            split2(f.x * 0.125f, f.y * 0.125f, hw[2 * j],     lw[2 * j]);
            split2(f.z * 0.125f, f.w * 0.125f, hw[2 * j + 1], lw[2 * j + 1]);
        }
        char* dh = sb + A_QH + row * ARS + half * 64;
        char* dl = sb + A_QL + row * ARS + half * 64;
        #pragma unroll
        for (int j = 0; j < 4; j++) {
            *(uint4*)(dh + j * 16) = make_uint4(hw[4*j], hw[4*j+1], hw[4*j+2], hw[4*j+3]);
            *(uint4*)(dl + j * 16) = make_uint4(lw[4*j], lw[4*j+1], lw[4*j+2], lw[4*j+3]);
        }
    }
    __syncthreads();

    // ---- load Q fragments (once) ----
    uint32_t qh[4][4], ql[4][4];
    {
        uint32_t qa_h = sbase + A_QH + (uint32_t)(w * 16 + (lane & 15)) * ARS + (lane >> 4) * 16;
        uint32_t qa_l = qa_h + (A_QL - A_QH);
        #pragma unroll
        for (int ks = 0; ks < 4; ks++) {
            LDSM4(qh[ks], qa_h + ks * 32);
            LDSM4(ql[ks], qa_l + ks * 32);
        }
    }

    // ---- per-row online softmax state + ctx accumulators ----
    float m0 = -1e30f, m1 = -1e30f, l0 = 0.f, l1 = 0.f;
    float co[8][4];
    #pragma unroll
    for (int nd = 0; nd < 8; nd++)
        #pragma unroll
        for (int t = 0; t < 4; t++) co[nd][t] = 0.f;

    bool dense = (qb == 0) || (qb == NB - 1);
    int nkb = dense ? NB : 8;
    int blist[8];
    if (!dense) {
        blist[0] = 0; blist[1] = qb - 1; blist[2] = qb; blist[3] = qb + 1;
        blist[4] = NB - 1;
        const int* rp = rb + (h * NB + qb) * RR;
        blist[5] = rp[0]; blist[6] = rp[1]; blist[7] = rp[2];
    }

    int srow = tid >> 1, shalf = tid & 1;            // staging thread mapping
    uint32_t kb_h = sbase + A_KH + (uint32_t)(lane & 7) * ARS + ((lane >> 3) & 1) * 16;
    uint32_t vb_h = sbase + A_VH + (uint32_t)(lane & 7) * ARS + ((lane >> 3) & 1) * 16;

    for (int jb = 0; jb < nkb; jb++) {
        int kb = dense ? jb : blist[jb];
        size_t base = ((size_t)(b * SEQ + kb * BLKS + srow)) * Dm + h * DHd + shalf * 32;
        __syncthreads();     // prior-iteration reads complete
        // stage K [key][d]
        {
            const float4* src = (const float4*)(k + base);
            uint32_t hw[16], lw[16];
            #pragma unroll
            for (int j = 0; j < 8; j++) {
                float4 f = src[j];
                split2(f.x, f.y, hw[2 * j],     lw[2 * j]);
                split2(f.z, f.w, hw[2 * j + 1], lw[2 * j + 1]);
            }
            char* dh = sb + A_KH + srow * ARS + shalf * 64;
            char* dl = sb + A_KL + srow * ARS + shalf * 64;
            #pragma unroll
            for (int j = 0; j < 4; j++) {
                *(uint4*)(dh + j * 16) = make_uint4(hw[4*j], hw[4*j+1], hw[4*j+2], hw[4*j+3]);
                *(uint4*)(dl + j * 16) = make_uint4(lw[4*j], lw[4*j+1], lw[4*j+2], lw[4*j+3]);
            }
        }
        // stage V transposed [d][key]
        {
            const float4* src = (const float4*)(v + base);
            #pragma unroll
            for (int j = 0; j < 8; j++) {
                float4 f = src[j];
                float vals[4] = {f.x, f.y, f.z, f.w};
                #pragma unroll
                for (int c = 0; c < 4; c++) {
                    int d = shalf * 32 + j * 4 + c;
                    __nv_bfloat16 hv = __float2bfloat16_rn(vals[c]);
                    *(__nv_bfloat16*)(sb + A_VH + d * ARS + srow * 2) = hv;
                    *(__nv_bfloat16*)(sb + A_VL + d * ARS + srow * 2) =
                        __float2bfloat16_rn(vals[c] - __bfloat162float(hv));
                }
            }
        }
        __syncthreads();

        // ---- S = Qs @ K^T  (16 x 64 per warp) ----
        float sc[8][4];
        #pragma unroll
        for (int ni = 0; ni < 8; ni++)
            #pragma unroll
            for (int t = 0; t < 4; t++) sc[ni][t] = 0.f;
        #pragma unroll
        for (int ni = 0; ni < 8; ni++) {
            uint32_t ba_h = kb_h + (uint32_t)(ni * 8) * ARS;
            uint32_t ba_l = ba_h + (A_KL - A_KH);
            #pragma unroll
            for (int ks = 0; ks < 4; ks++) {
                uint32_t bh0, bh1, bl0, bl1;
                LDSM2(bh0, bh1, ba_h + ks * 32);
                LDSM2(bl0, bl1, ba_l + ks * 32);
                mma16816(sc[ni], qh[ks], bh0, bh1);
                mma16816(sc[ni], qh[ks], bl0, bl1);
                mma16816(sc[ni], ql[ks], bh0, bh1);
            }
        }

        // ---- online softmax (rows g and g+8 per thread) ----
        float bm0 = -1e30f, bm1 = -1e30f;
        #pragma unroll
        for (int ni = 0; ni < 8; ni++) {
            bm0 = fmaxf(bm0, fmaxf(sc[ni][0], sc[ni][1]));
            bm1 = fmaxf(bm1, fmaxf(sc[ni][2], sc[ni][3]));
        }
        bm0 = fmaxf(bm0, __shfl_xor_sync(0xffffffffu, bm0, 1));
        bm0 = fmaxf(bm0, __shfl_xor_sync(0xffffffffu, bm0, 2));
        bm1 = fmaxf(bm1, __shfl_xor_sync(0xffffffffu, bm1, 1));
        bm1 = fmaxf(bm1, __shfl_xor_sync(0xffffffffu, bm1, 2));
        float mn0 = fmaxf(m0, bm0), mn1 = fmaxf(m1, bm1);
        float corr0 = __expf(m0 - mn0), corr1 = __expf(m1 - mn1);
        m0 = mn0; m1 = mn1;
        #pragma unroll
        for (int nd = 0; nd < 8; nd++) {
            co[nd][0] *= corr0; co[nd][1] *= corr0;
            co[nd][2] *= corr1; co[nd][3] *= corr1;
        }
        float ls0 = 0.f, ls1 = 0.f;
        #pragma unroll
        for (int ni = 0; ni < 8; ni++) {
            sc[ni][0] = __expf(sc[ni][0] - mn0);
            sc[ni][1] = __expf(sc[ni][1] - mn0);
            sc[ni][2] = __expf(sc[ni][2] - mn1);
            sc[ni][3] = __expf(sc[ni][3] - mn1);
            ls0 += sc[ni][0] + sc[ni][1];
            ls1 += sc[ni][2] + sc[ni][3];
        }
        ls0 += __shfl_xor_sync(0xffffffffu, ls0, 1);
        ls0 += __shfl_xor_sync(0xffffffffu, ls0, 2);
        ls1 += __shfl_xor_sync(0xffffffffu, ls1, 1);
        ls1 += __shfl_xor_sync(0xffffffffu, ls1, 2);
        l0 = l0 * corr0 + ls0;
        l1 = l1 * corr1 + ls1;

        // ---- P fragments (C-layout == A-layout) ----
        uint32_t pah[4][4], pal[4][4];
        #pragma unroll
        for (int ksp = 0; ksp < 4; ksp++) {
            split2(sc[2*ksp][0],   sc[2*ksp][1],   pah[ksp][0], pal[ksp][0]);
            split2(sc[2*ksp][2],   sc[2*ksp][3],   pah[ksp][1], pal[ksp][1]);
            split2(sc[2*ksp+1][0], sc[2*ksp+1][1], pah[ksp][2], pal[ksp][2]);
            split2(sc[2*ksp+1][2], sc[2*ksp+1][3], pah[ksp][3], pal[ksp][3]);
        }

        // ---- ctx += P @ V  (V^T tiles as B) ----
        #pragma unroll
        for (int nd = 0; nd < 8; nd++) {
            uint32_t va_h = vb_h + (uint32_t)(nd * 8) * ARS;
            uint32_t va_l = va_h + (A_VL - A_VH);
            #pragma unroll
            for (int ksp = 0; ksp < 4; ksp++) {
                uint32_t vh0, vh1, vl0, vl1;
                LDSM2(vh0, vh1, va_h + ksp * 32);
                LDSM2(vl0, vl1, va_l + ksp * 32);
                mma16816(co[nd], pah[ksp], vh0, vh1);
                mma16816(co[nd], pah[ksp], vl0, vl1);
                mma16816(co[nd], pal[ksp], vh0, vh1);
            }
        }
    }

    // ---- write out ----
    float inv0 = 1.f / l0, inv1 = 1.f / l1;
    int g = lane >> 2, t4 = lane & 3;
    size_t rbase = ((size_t)(b * SEQ + qb * BLKS + w * 16 + g)) * Dm + h * DHd;
    #pragma unroll
    for (int nd = 0; nd < 8; nd++) {
        int col = nd * 8 + 2 * t4;
        float2 o0, o1;
        o0.x = co[nd][0] * inv0; o0.y = co[nd][1] * inv0;
        o1.x = co[nd][2] * inv1; o1.y = co[nd][3] * inv1;
        *(float2*)(out + rbase + col)          = o0;
        *(float2*)(out + rbase + 8 * Dm + col) = o1;
    }
}

// ---------------- mean pool + linear head (two stage) ----------------
__global__ void __launch_bounds__(256) pool1_kernel(
    const float* __restrict__ x, const float* __restrict__ w, float* __restrict__ part)
{
    int b = blockIdx.y, sl = blockIdx.x;
    const float* xb = x + ((size_t)b * SEQ + sl * 128) * Dm;
    __shared__ float ws[Dm];
    for (int i = threadIdx.x; i < Dm; i += 256) ws[i] = w[i];
    __syncthreads();
    float acc = 0.f;
    for (int r = 0; r < 128; r++) {
        const float* xr = xb + (size_t)r * Dm;
        for (int i = threadIdx.x; i < Dm; i += 256) acc += xr[i] * ws[i];
    }
    float t = blk_sum256(acc);
    if (threadIdx.x == 0) part[b * 32 + sl] = t;
}
__global__ void pool2_kernel(const float* __restrict__ part,
                             const float* __restrict__ fb, float* __restrict__ out)
{
    int b = threadIdx.x;
    if (b < BB) {
        float s = 0.f;
        for (int i = 0; i < 32; i++) s += part[b * 32 + i];
        out[b] = s * (1.f / (float)SEQ) + fb[0];
    }
}

// ---------------- driver ----------------
extern "C" void kernel_launch(void* const* d_in, const int* in_sizes, int n_in,
                              void* d_out, int out_size)
{
    const int*   ids     = (const int*)  d_in[0];
    const int*   rb      = (const int*)  d_in[1];
    const float* emb_tok = (const float*)d_in[2];
    const float* emb_pos = (const float*)d_in[3];
    const float* lng     = (const float*)d_in[4];
    const float* lnb     = (const float*)d_in[5];
    const float* Wq = (const float*)d_in[6];  const float* bq = (const float*)d_in[7];
    const float* Wk = (const float*)d_in[8];  const float* bk = (const float*)d_in[9];
    const float* Wv = (const float*)d_in[10]; const float* bv = (const float*)d_in[11];
    const float* Wo = (const float*)d_in[12]; const float* bo = (const float*)d_in[13];
    const float* ln1g = (const float*)d_in[14]; const float* ln1b = (const float*)d_in[15];
    const float* W1 = (const float*)d_in[16]; const float* b1 = (const float*)d_in[17];
    const float* W2 = (const float*)d_in[18]; const float* b2 = (const float*)d_in[19];
    const float* ln2g = (const float*)d_in[20]; const float* ln2b = (const float*)d_in[21];
    const float* fcw = (const float*)d_in[22]; const float* fcb = (const float*)d_in[23];

    float *x, *q, *k, *v, *ctx, *tmp, *ffn, *part;
    __nv_bfloat16 *wh, *wl;
    cudaGetSymbolAddress((void**)&x,   g_x);
    cudaGetSymbolAddress((void**)&q,   g_q);
    cudaGetSymbolAddress((void**)&k,   g_k);
    cudaGetSymbolAddress((void**)&v,   g_v);
    cudaGetSymbolAddress((void**)&ctx, g_ctx);
    cudaGetSymbolAddress((void**)&tmp, g_tmp);
    cudaGetSymbolAddress((void**)&ffn, g_ffn);
    cudaGetSymbolAddress((void**)&wh,  g_wh);
    cudaGetSymbolAddress((void**)&wl,  g_wl);
    cudaGetSymbolAddress((void**)&part, g_part);

    const int SMEM_GEMM = 2 * STG_B;
    cudaFuncSetAttribute((const void*)gemm_mma<0>,
                         cudaFuncAttributeMaxDynamicSharedMemorySize, SMEM_GEMM);
    cudaFuncSetAttribute((const void*)gemm_mma<1>,
                         cudaFuncAttributeMaxDynamicSharedMemorySize, SMEM_GEMM);
    cudaFuncSetAttribute((const void*)attn_mma_kernel,
                         cudaFuncAttributeMaxDynamicSharedMemorySize, A_SMEM);

    dim3 gN(Dm / 128, NTOK / 128);
    dim3 gF(FF / 128, NTOK / 128);
    dim3 gAtt(NB, Hh, BB);
    dim3 gWS(Dm / 32, Dm / 32);

    // launch 0
    embed_ln_kernel<<<NTOK, 256>>>(ids, emb_tok, emb_pos, lng, lnb, x);

    for (int l = 0; l < 2; l++) {
        size_t o = (size_t)l * OFFL;
        // qkv weight split (one launch; launch index 1 for l=0)
        wsplit3_kernel<<<dim3(Dm / 32, Dm / 32, 3), 256>>>(
            Wq + (size_t)l * WSZ, Wk + (size_t)l * WSZ, Wv + (size_t)l * WSZ,
            wh + o, wl + o);
        gemm_mma<0><<<gN, 256, SMEM_GEMM>>>(x, wh + o,           wl + o,           bq + l * Dm, q, NTOK, Dm, Dm);
        gemm_mma<0><<<gN, 256, SMEM_GEMM>>>(x, wh + o + WSZ,     wl + o + WSZ,     bk + l * Dm, k, NTOK, Dm, Dm);
        gemm_mma<0><<<gN, 256, SMEM_GEMM>>>(x, wh + o + 2 * WSZ, wl + o + 2 * WSZ, bv + l * Dm, v, NTOK, Dm, Dm);
        // launch index 5 (l=0): attention — profiled by ncu
        attn_mma_kernel<<<gAtt, 128, A_SMEM>>>(q, k, v, rb, ctx);
        wsplit_kernel<<<gWS, 256>>>(Wo + (size_t)l * WSZ, wh + o + 3 * WSZ, wl + o + 3 * WSZ, Dm, Dm);
        gemm_mma<0><<<gN, 256, SMEM_GEMM>>>(ctx, wh + o + 3 * WSZ, wl + o + 3 * WSZ, bo + l * Dm, tmp, NTOK, Dm, Dm);
        add_ln_kernel<<<NTOK, 256>>>(x, tmp, ln1g + l * Dm, ln1b + l * Dm);
        wsplit_kernel<<<dim3(FF / 32, Dm / 32), 256>>>(W1 + (size_t)l * W1SZ, wh + o + 4 * WSZ, wl + o + 4 * WSZ, Dm, FF);
        gemm_mma<1><<<gF, 256, SMEM_GEMM>>>(x, wh + o + 4 * WSZ, wl + o + 4 * WSZ, b1 + l * FF, ffn, NTOK, FF, Dm);
        wsplit_kernel<<<dim3(Dm / 32, FF / 32), 256>>>(W2 + (size_t)l * W1SZ, wh + o + 4 * WSZ + W1SZ, wl + o + 4 * WSZ + W1SZ, FF, Dm);
        gemm_mma<0><<<gN, 256, SMEM_GEMM>>>(ffn, wh + o + 4 * WSZ + W1SZ, wl + o + 4 * WSZ + W1SZ, b2 + l * Dm, tmp, NTOK, Dm, FF);
        add_ln_kernel<<<NTOK, 256>>>(x, tmp, ln2g + l * Dm, ln2b + l * Dm);
    }

    pool1_kernel<<<dim3(32, BB), 256>>>(x, fcw, part);
    pool2_kernel<<<1, 32>>>(part, fcb, (float*)d_out);
}

// round 6
// speedup vs baseline: 5.4566x; 1.8438x over previous
#include <cuda_runtime.h>
#include <cuda_bf16.h>
#include <math.h>
#include <stdint.h>

// ---------------- problem constants ----------------
#define Dm   768
#define Hh   12
#define DHd  64
#define BLKS 64
#define NB   64
#define SEQ  4096
#define BB   2
#define NTOK (BB*SEQ)
#define RR   3
#define FF   3072

#define WSZ   589824
#define W1SZ  2359296
#define OFFL  (4*WSZ + 2*W1SZ)

// ---------------- scratch (device globals) ----------------
__device__ float g_x  [NTOK*Dm];
__device__ float g_tmp[NTOK*Dm];
__device__ __nv_bfloat16 g_xh [NTOK*Dm];
__device__ __nv_bfloat16 g_xl [NTOK*Dm];
__device__ __nv_bfloat16 g_qh [NTOK*Dm];
__device__ __nv_bfloat16 g_ql [NTOK*Dm];
__device__ __nv_bfloat16 g_kh [NTOK*Dm];
__device__ __nv_bfloat16 g_kl [NTOK*Dm];
__device__ __nv_bfloat16 g_vh [NTOK*Dm];
__device__ __nv_bfloat16 g_vl [NTOK*Dm];
__device__ __nv_bfloat16 g_ch [NTOK*Dm];
__device__ __nv_bfloat16 g_cl [NTOK*Dm];
__device__ __nv_bfloat16 g_fh [NTOK*FF];
__device__ __nv_bfloat16 g_fl [NTOK*FF];
__device__ __nv_bfloat16 g_wh [2*OFFL];
__device__ __nv_bfloat16 g_wl [2*OFFL];
__device__ float g_part[64];

// ---------------- helpers ----------------
__device__ __forceinline__ float gelu_tanh(float x) {
    float x3 = x * x * x;
    return 0.5f * x * (1.f + tanhf(0.7978845608028654f * (x + 0.044715f * x3)));
}

__device__ __forceinline__ float blk_sum256(float v) {
    __shared__ float red[32];
    int lane = threadIdx.x & 31, wid = threadIdx.x >> 5;
    #pragma unroll
    for (int o = 16; o > 0; o >>= 1) v += __shfl_xor_sync(0xffffffffu, v, o);
    if (lane == 0) red[wid] = v;
    __syncthreads();
    if (wid == 0) {
        v = (lane < 8) ? red[lane] : 0.f;
        #pragma unroll
        for (int o = 4; o > 0; o >>= 1) v += __shfl_xor_sync(0xffffffffu, v, o);
        if (lane == 0) red[0] = v;
    }
    __syncthreads();
    float r = red[0];
    __syncthreads();
    return r;
}

__device__ __forceinline__ uint32_t s2u(const void* p) {
    uint32_t a;
    asm("{ .reg .u64 t; cvta.to.shared.u64 t, %1; cvt.u32.u64 %0, t; }" : "=r"(a) : "l"(p));
    return a;
}

#define LDSM4(r, a) \
    asm volatile("ldmatrix.sync.aligned.m8n8.x4.shared.b16 {%0,%1,%2,%3}, [%4];" \
        : "=r"((r)[0]), "=r"((r)[1]), "=r"((r)[2]), "=r"((r)[3]) : "r"(a))
#define LDSM2(r0, r1, a) \
    asm volatile("ldmatrix.sync.aligned.m8n8.x2.shared.b16 {%0,%1}, [%2];" \
        : "=r"(r0), "=r"(r1) : "r"(a))
#define LDSM2T(r0, r1, a) \
    asm volatile("ldmatrix.sync.aligned.m8n8.x2.trans.shared.b16 {%0,%1}, [%2];" \
        : "=r"(r0), "=r"(r1) : "r"(a))

#define CPA16(dst, src) \
    asm volatile("cp.async.cg.shared.global [%0], [%1], 16;" :: "r"(dst), "l"(src))
#define CP_COMMIT() asm volatile("cp.async.commit_group;" ::: "memory")
#define CP_WAIT(n)  asm volatile("cp.async.wait_group %0;" :: "n"(n) : "memory")

__device__ __forceinline__ void mma16816(float* c, const uint32_t* a,
                                         uint32_t b0, uint32_t b1) {
    asm volatile(
        "mma.sync.aligned.m16n8k16.row.col.f32.bf16.bf16.f32 "
        "{%0,%1,%2,%3}, {%4,%5,%6,%7}, {%8,%9}, {%0,%1,%2,%3};"
        : "+f"(c[0]), "+f"(c[1]), "+f"(c[2]), "+f"(c[3])
        : "r"(a[0]), "r"(a[1]), "r"(a[2]), "r"(a[3]), "r"(b0), "r"(b1));
}

__device__ __forceinline__ void split2(float a, float b, uint32_t& hi, uint32_t& lo) {
    __nv_bfloat16 ha = __float2bfloat16_rn(a);
    __nv_bfloat16 hb = __float2bfloat16_rn(b);
    __nv_bfloat16 la = __float2bfloat16_rn(a - __bfloat162float(ha));
    __nv_bfloat16 lb = __float2bfloat16_rn(b - __bfloat162float(hb));
    hi = (uint32_t)__bfloat16_as_ushort(ha) | ((uint32_t)__bfloat16_as_ushort(hb) << 16);
    lo = (uint32_t)__bfloat16_as_ushort(la) | ((uint32_t)__bfloat16_as_ushort(lb) << 16);
}

// ---------------- weight transpose + split ----------------
__global__ void __launch_bounds__(256) wsplit_kernel(
    const float* __restrict__ W, __nv_bfloat16* __restrict__ hi,
    __nv_bfloat16* __restrict__ lo, int K, int N)
{
    __shared__ float t[32][33];
    int n0 = blockIdx.x * 32, k0 = blockIdx.y * 32;
    int tx = threadIdx.x & 31, ty = threadIdx.x >> 5;
    #pragma unroll
    for (int j = 0; j < 4; j++)
        t[ty + j * 8][tx] = W[(size_t)(k0 + ty + j * 8) * N + n0 + tx];
    __syncthreads();
    #pragma unroll
    for (int j = 0; j < 4; j++) {
        int n = n0 + ty + j * 8, k = k0 + tx;
        float v = t[tx][ty + j * 8];
        __nv_bfloat16 h = __float2bfloat16_rn(v);
        hi[(size_t)n * K + k] = h;
        lo[(size_t)n * K + k] = __float2bfloat16_rn(v - __bfloat162float(h));
    }
}

__global__ void __launch_bounds__(256) wsplit3_kernel(
    const float* __restrict__ Wa, const float* __restrict__ Wb,
    const float* __restrict__ Wc, __nv_bfloat16* __restrict__ hi,
    __nv_bfloat16* __restrict__ lo)
{
    __shared__ float t[32][33];
    int z = blockIdx.z;
    const float* W = (z == 0) ? Wa : (z == 1) ? Wb : Wc;
    __nv_bfloat16* hz = hi + (size_t)z * WSZ;
    __nv_bfloat16* lz = lo + (size_t)z * WSZ;
    int n0 = blockIdx.x * 32, k0 = blockIdx.y * 32;
    int tx = threadIdx.x & 31, ty = threadIdx.x >> 5;
    #pragma unroll
    for (int j = 0; j < 4; j++)
        t[ty + j * 8][tx] = W[(size_t)(k0 + ty + j * 8) * Dm + n0 + tx];
    __syncthreads();
    #pragma unroll
    for (int j = 0; j < 4; j++) {
        int n = n0 + ty + j * 8, k = k0 + tx;
        float v = t[tx][ty + j * 8];
        __nv_bfloat16 h = __float2bfloat16_rn(v);
        hz[(size_t)n * Dm + k] = h;
        lz[(size_t)n * Dm + k] = __float2bfloat16_rn(v - __bfloat162float(h));
    }
}

// ---------------- cp.async warp-MMA GEMM ----------------
// A hi/lo bf16 [M,K]; B hi/lo bf16 [N,K]; out: fp32 C and/or bf16 hi/lo.
#define RS_B   80
#define TILE_B (128*RS_B)
#define STG_B  (4*TILE_B)

template<int GELU, int WF32, int WSPL>
__global__ void __launch_bounds__(256, 2) gemm_mma(
    const __nv_bfloat16* __restrict__ Ahi, const __nv_bfloat16* __restrict__ Alo,
    const __nv_bfloat16* __restrict__ Bhi, const __nv_bfloat16* __restrict__ Blo,
    const float* __restrict__ bias, float* __restrict__ C,
    __nv_bfloat16* __restrict__ Chi, __nv_bfloat16* __restrict__ Clo,
    int M, int N, int K)
{
    extern __shared__ char sm[];
    uint32_t sbase = s2u(sm);
    int tid = threadIdx.x, lane = tid & 31, wid = tid >> 5;
    int m0 = blockIdx.y * 128, n0 = blockIdx.x * 128;
    int wm = (wid & 3) * 32, wn = (wid >> 2) * 64;

    int lr = tid & 127, lh = tid >> 7;
    const __nv_bfloat16* ah_p = Ahi + (size_t)(m0 + lr) * K + lh * 16;
    const __nv_bfloat16* al_p = Alo + (size_t)(m0 + lr) * K + lh * 16;
    const __nv_bfloat16* bh_p = Bhi + (size_t)(n0 + lr) * K + lh * 16;
    const __nv_bfloat16* bl_p = Blo + (size_t)(n0 + lr) * K + lh * 16;
    uint32_t woff = (uint32_t)lr * RS_B + (uint32_t)lh * 32;

    float acc[2][8][4];
    #pragma unroll
    for (int i = 0; i < 2; i++)
        #pragma unroll
        for (int j = 0; j < 8; j++)
            #pragma unroll
            for (int t = 0; t < 4; t++) acc[i][j][t] = 0.f;

    int chunks = K >> 5;

    // prologue: issue chunk 0
    {
        uint32_t d = sbase + woff;
        CPA16(d,                  ah_p);     CPA16(d + 16,              ah_p + 8);
        CPA16(d + TILE_B,         al_p);     CPA16(d + TILE_B + 16,     al_p + 8);
        CPA16(d + 2 * TILE_B,     bh_p);     CPA16(d + 2 * TILE_B + 16, bh_p + 8);
        CPA16(d + 3 * TILE_B,     bl_p);     CPA16(d + 3 * TILE_B + 16, bl_p + 8);
        CP_COMMIT();
    }

    int r16 = lane & 15, c16 = lane >> 4;
    int r8  = lane & 7,  c8  = (lane >> 3) & 1;

    for (int c = 0; c < chunks; c++) {
        if (c + 1 < chunks) {
            uint32_t d = sbase + ((c + 1) & 1) * STG_B + woff;
            int off = (c + 1) * 32;
            CPA16(d,                  ah_p + off);     CPA16(d + 16,              ah_p + off + 8);
            CPA16(d + TILE_B,         al_p + off);     CPA16(d + TILE_B + 16,     al_p + off + 8);
            CPA16(d + 2 * TILE_B,     bh_p + off);     CPA16(d + 2 * TILE_B + 16, bh_p + off + 8);
            CPA16(d + 3 * TILE_B,     bl_p + off);     CPA16(d + 3 * TILE_B + 16, bl_p + off + 8);
            CP_COMMIT();
            CP_WAIT(1);
        } else {
            CP_WAIT(0);
        }
        __syncthreads();
        {
            uint32_t base = sbase + (c & 1) * STG_B;
            #pragma unroll
            for (int ks = 0; ks < 2; ks++) {
                uint32_t ah[2][4], al[2][4];
                #pragma unroll
                for (int mi = 0; mi < 2; mi++) {
                    uint32_t rel = (uint32_t)(wm + mi * 16 + r16) * RS_B
                                 + ks * 32 + c16 * 16;
                    LDSM4(ah[mi], base + rel);
                    LDSM4(al[mi], base + TILE_B + rel);
                }
                #pragma unroll
                for (int ni = 0; ni < 8; ni++) {
                    uint32_t rel = (uint32_t)(wn + ni * 8 + r8) * RS_B
                                 + ks * 32 + c8 * 16;
                    uint32_t bh0, bh1, bl0, bl1;
                    LDSM2(bh0, bh1, base + 2 * TILE_B + rel);
                    LDSM2(bl0, bl1, base + 3 * TILE_B + rel);
                    #pragma unroll
                    for (int mi = 0; mi < 2; mi++) {
                        mma16816(acc[mi][ni], ah[mi], bh0, bh1);
                        mma16816(acc[mi][ni], ah[mi], bl0, bl1);
                        mma16816(acc[mi][ni], al[mi], bh0, bh1);
                    }
                }
            }
        }
        __syncthreads();
    }

    // epilogue
    int g = lane >> 2, t4 = lane & 3;
    #pragma unroll
    for (int mi = 0; mi < 2; mi++) {
        int row0 = m0 + wm + mi * 16 + g;
        #pragma unroll
        for (int ni = 0; ni < 8; ni++) {
            int col = n0 + wn + ni * 8 + 2 * t4;
            float2 bi = *(const float2*)(bias + col);
            float2 o0, o1;
            o0.x = acc[mi][ni][0] + bi.x;
            o0.y = acc[mi][ni][1] + bi.y;
            o1.x = acc[mi][ni][2] + bi.x;
            o1.y = acc[mi][ni][3] + bi.y;
            if (GELU) {
                o0.x = gelu_tanh(o0.x); o0.y = gelu_tanh(o0.y);
                o1.x = gelu_tanh(o1.x); o1.y = gelu_tanh(o1.y);
            }
            size_t i0 = (size_t)row0 * N + col;
            size_t i1 = (size_t)(row0 + 8) * N + col;
            if (WF32) {
                *(float2*)(C + i0) = o0;
                *(float2*)(C + i1) = o1;
            }
            if (WSPL) {
                uint32_t h0, l0, h1, l1;
                split2(o0.x, o0.y, h0, l0);
                split2(o1.x, o1.y, h1, l1);
                *(uint32_t*)(Chi + i0) = h0;
                *(uint32_t*)(Clo + i0) = l0;
                *(uint32_t*)(Chi + i1) = h1;
                *(uint32_t*)(Clo + i1) = l1;
            }
        }
    }
}

// ---------------- embedding + LN (writes fp32 + hi/lo) ----------------
__global__ void __launch_bounds__(256) embed_ln_kernel(
    const int* __restrict__ ids, const float* __restrict__ tok,
    const float* __restrict__ pos, const float* __restrict__ g,
    const float* __restrict__ b, float* __restrict__ x,
    __nv_bfloat16* __restrict__ xh, __nv_bfloat16* __restrict__ xl)
{
    int t = blockIdx.x, s = t & (SEQ - 1), id = ids[t];
    float val[3];
    #pragma unroll
    for (int j = 0; j < 3; j++) {
        int i = threadIdx.x + j * 256;
        val[j] = tok[(size_t)id * Dm + i] + pos[(size_t)s * Dm + i];
    }
    float mean = blk_sum256(val[0] + val[1] + val[2]) * (1.f / 768.f);
    float sq = 0.f;
    #pragma unroll
    for (int j = 0; j < 3; j++) { float d = val[j] - mean; sq += d * d; }
    float rstd = rsqrtf(blk_sum256(sq) * (1.f / 768.f) + 1e-12f);
    #pragma unroll
    for (int j = 0; j < 3; j++) {
        int i = threadIdx.x + j * 256;
        float o = (val[j] - mean) * rstd * g[i] + b[i];
        size_t idx = (size_t)t * Dm + i;
        x[idx] = o;
        __nv_bfloat16 h = __float2bfloat16_rn(o);
        xh[idx] = h;
        xl[idx] = __float2bfloat16_rn(o - __bfloat162float(h));
    }
}

// ---------------- residual add + LN (writes fp32 + hi/lo) ----------------
__global__ void __launch_bounds__(256) add_ln_kernel(
    float* __restrict__ x, const float* __restrict__ y,
    const float* __restrict__ g, const float* __restrict__ b,
    __nv_bfloat16* __restrict__ xh, __nv_bfloat16* __restrict__ xl)
{
    size_t t = blockIdx.x;
    float* xp = x + t * Dm;
    const float* yp = y + t * Dm;
    float val[3];
    #pragma unroll
    for (int j = 0; j < 3; j++) {
        int i = threadIdx.x + j * 256;
        val[j] = xp[i] + yp[i];
    }
    float mean = blk_sum256(val[0] + val[1] + val[2]) * (1.f / 768.f);
    float sq = 0.f;
    #pragma unroll
    for (int j = 0; j < 3; j++) { float d = val[j] - mean; sq += d * d; }
    float rstd = rsqrtf(blk_sum256(sq) * (1.f / 768.f) + 1e-12f);
    #pragma unroll
    for (int j = 0; j < 3; j++) {
        int i = threadIdx.x + j * 256;
        float o = (val[j] - mean) * rstd * g[i] + b[i];
        xp[i] = o;
        __nv_bfloat16 h = __float2bfloat16_rn(o);
        xh[t * Dm + i] = h;
        xl[t * Dm + i] = __float2bfloat16_rn(o - __bfloat162float(h));
    }
}

// ---------------- BigBird attention (HMMA, pre-split inputs) ----------------
#define ARS 144
#define A_QH 0
#define A_QL 9216
#define A_KH 18432
#define A_KL 27648
#define A_VH 36864
#define A_VL 46080
#define A_SMEM 55296

__global__ void __launch_bounds__(128) attn_mma_kernel(
    const __nv_bfloat16* __restrict__ qh_g, const __nv_bfloat16* __restrict__ ql_g,
    const __nv_bfloat16* __restrict__ kh_g, const __nv_bfloat16* __restrict__ kl_g,
    const __nv_bfloat16* __restrict__ vh_g, const __nv_bfloat16* __restrict__ vl_g,
    const int* __restrict__ rb,
    __nv_bfloat16* __restrict__ ch_g, __nv_bfloat16* __restrict__ cl_g)
{
    extern __shared__ char sb[];
    uint32_t sbase = s2u(sb);
    int b = blockIdx.z, h = blockIdx.y, qb = blockIdx.x;
    int tid = threadIdx.x, lane = tid & 31, w = tid >> 5;

    int srow = tid >> 1, shalf = tid & 1;
    // stage Q hi/lo via cp.async
    {
        size_t off = ((size_t)(b * SEQ + qb * BLKS + srow)) * Dm + h * DHd + shalf * 32;
        uint32_t dh = sbase + A_QH + (uint32_t)srow * ARS + shalf * 64;
        uint32_t dl = sbase + A_QL + (uint32_t)srow * ARS + shalf * 64;
        CPA16(dh,      qh_g + off);      CPA16(dh + 16, qh_g + off + 8);
        CPA16(dh + 32, qh_g + off + 16); CPA16(dh + 48, qh_g + off + 24);
        CPA16(dl,      ql_g + off);      CPA16(dl + 16, ql_g + off + 8);
        CPA16(dl + 32, ql_g + off + 16); CPA16(dl + 48, ql_g + off + 24);
        CP_COMMIT(); CP_WAIT(0);
    }
    __syncthreads();

    uint32_t qfh[4][4], qfl[4][4];
    {
        uint32_t qa_h = sbase + A_QH + (uint32_t)(w * 16 + (lane & 15)) * ARS + (lane >> 4) * 16;
        uint32_t qa_l = qa_h + (A_QL - A_QH);
        #pragma unroll
        for (int ks = 0; ks < 4; ks++) {
            LDSM4(qfh[ks], qa_h + ks * 32);
            LDSM4(qfl[ks], qa_l + ks * 32);
        }
    }

    float m0 = -1e30f, m1 = -1e30f, l0 = 0.f, l1 = 0.f;
    float co[8][4];
    #pragma unroll
    for (int nd = 0; nd < 8; nd++)
        #pragma unroll
        for (int t = 0; t < 4; t++) co[nd][t] = 0.f;

    bool dense = (qb == 0) || (qb == NB - 1);
    int nkb = dense ? NB : 8;
    int blist[8];
    if (!dense) {
        blist[0] = 0; blist[1] = qb - 1; blist[2] = qb; blist[3] = qb + 1;
        blist[4] = NB - 1;
        const int* rp = rb + (h * NB + qb) * RR;
        blist[5] = rp[0]; blist[6] = rp[1]; blist[7] = rp[2];
    }

    uint32_t kb_h = sbase + A_KH + (uint32_t)(lane & 7) * ARS + ((lane >> 3) & 1) * 16;

    for (int jb = 0; jb < nkb; jb++) {
        int kb = dense ? jb : blist[jb];
        size_t base = ((size_t)(b * SEQ + kb * BLKS + srow)) * Dm + h * DHd + shalf * 32;
        __syncthreads();   // previous-iteration reads complete
        {
            uint32_t dk = sbase + A_KH + (uint32_t)srow * ARS + shalf * 64;
            uint32_t dv = sbase + A_VH + (uint32_t)srow * ARS + shalf * 64;
            CPA16(dk,      kh_g + base);      CPA16(dk + 16, kh_g + base + 8);
            CPA16(dk + 32, kh_g + base + 16); CPA16(dk + 48, kh_g + base + 24);
            uint32_t dkl = dk + (A_KL - A_KH);
            CPA16(dkl,      kl_g + base);      CPA16(dkl + 16, kl_g + base + 8);
            CPA16(dkl + 32, kl_g + base + 16); CPA16(dkl + 48, kl_g + base + 24);
            CPA16(dv,      vh_g + base);      CPA16(dv + 16, vh_g + base + 8);
            CPA16(dv + 32, vh_g + base + 16); CPA16(dv + 48, vh_g + base + 24);
            uint32_t dvl = dv + (A_VL - A_VH);
            CPA16(dvl,      vl_g + base);      CPA16(dvl + 16, vl_g + base + 8);
            CPA16(dvl + 32, vl_g + base + 16); CPA16(dvl + 48, vl_g + base + 24);
            CP_COMMIT(); CP_WAIT(0);
        }
        __syncthreads();

        // S = Q @ K^T
        float sc[8][4];
        #pragma unroll
        for (int ni = 0; ni < 8; ni++)
            #pragma unroll
            for (int t = 0; t < 4; t++) sc[ni][t] = 0.f;
        #pragma unroll
        for (int ni = 0; ni < 8; ni++) {
            uint32_t ba_h = kb_h + (uint32_t)(ni * 8) * ARS;
            uint32_t ba_l = ba_h + (A_KL - A_KH);
            #pragma unroll
            for (int ks = 0; ks < 4; ks++) {
                uint32_t bh0, bh1, bl0, bl1;
                LDSM2(bh0, bh1, ba_h + ks * 32);
                LDSM2(bl0, bl1, ba_l + ks * 32);
                mma16816(sc[ni], qfh[ks], bh0, bh1);
                mma16816(sc[ni], qfh[ks], bl0, bl1);
                mma16816(sc[ni], qfl[ks], bh0, bh1);
            }
        }
        #pragma unroll
        for (int ni = 0; ni < 8; ni++) {
            sc[ni][0] *= 0.125f; sc[ni][1] *= 0.125f;
            sc[ni][2] *= 0.125f; sc[ni][3] *= 0.125f;
        }

        // online softmax
        float bm0 = -1e30f, bm1 = -1e30f;
        #pragma unroll
        for (int ni = 0; ni < 8; ni++) {
            bm0 = fmaxf(bm0, fmaxf(sc[ni][0], sc[ni][1]));
            bm1 = fmaxf(bm1, fmaxf(sc[ni][2], sc[ni][3]));
        }
        bm0 = fmaxf(bm0, __shfl_xor_sync(0xffffffffu, bm0, 1));
        bm0 = fmaxf(bm0, __shfl_xor_sync(0xffffffffu, bm0, 2));
        bm1 = fmaxf(bm1, __shfl_xor_sync(0xffffffffu, bm1, 1));
        bm1 = fmaxf(bm1, __shfl_xor_sync(0xffffffffu, bm1, 2));
        float mn0 = fmaxf(m0, bm0), mn1 = fmaxf(m1, bm1);
        float corr0 = __expf(m0 - mn0), corr1 = __expf(m1 - mn1);
        m0 = mn0; m1 = mn1;
        #pragma unroll
        for (int nd = 0; nd < 8; nd++) {
            co[nd][0] *= corr0; co[nd][1] *= corr0;
            co[nd][2] *= corr1; co[nd][3] *= corr1;
        }
        float ls0 = 0.f, ls1 = 0.f;
        #pragma unroll
        for (int ni = 0; ni < 8; ni++) {
            sc[ni][0] = __expf(sc[ni][0] - mn0);
            sc[ni][1] = __expf(sc[ni][1] - mn0);
            sc[ni][2] = __expf(sc[ni][2] - mn1);
            sc[ni][3] = __expf(sc[ni][3] - mn1);
            ls0 += sc[ni][0] + sc[ni][1];
            ls1 += sc[ni][2] + sc[ni][3];
        }
        ls0 += __shfl_xor_sync(0xffffffffu, ls0, 1);
        ls0 += __shfl_xor_sync(0xffffffffu, ls0, 2);
        ls1 += __shfl_xor_sync(0xffffffffu, ls1, 1);
        ls1 += __shfl_xor_sync(0xffffffffu, ls1, 2);
        l0 = l0 * corr0 + ls0;
        l1 = l1 * corr1 + ls1;

        // P fragments
        uint32_t pah[4][4], pal[4][4];
        #pragma unroll
        for (int ksp = 0; ksp < 4; ksp++) {
            split2(sc[2*ksp][0],   sc[2*ksp][1],   pah[ksp][0], pal[ksp][0]);
            split2(sc[2*ksp][2],   sc[2*ksp][3],   pah[ksp][1], pal[ksp][1]);
            split2(sc[2*ksp+1][0], sc[2*ksp+1][1], pah[ksp][2], pal[ksp][2]);
            split2(sc[2*ksp+1][2], sc[2*ksp+1][3], pah[ksp][3], pal[ksp][3]);
        }

        // ctx += P @ V (B-frags via trans ldmatrix on [key][d] tiles)
        #pragma unroll
        for (int nd = 0; nd < 8; nd++) {
            #pragma unroll
            for (int ksp = 0; ksp < 4; ksp++) {
                uint32_t va = sbase + A_VH
                            + (uint32_t)(ksp * 16 + (lane & 15)) * ARS + nd * 16;
                uint32_t vh0, vh1, vl0, vl1;
                LDSM2T(vh0, vh1, va);
                LDSM2T(vl0, vl1, va + (A_VL - A_VH));
                mma16816(co[nd], pah[ksp], vh0, vh1);
                mma16816(co[nd], pah[ksp], vl0, vl1);
                mma16816(co[nd], pal[ksp], vh0, vh1);
            }
        }
    }

    // write ctx hi/lo
    float inv0 = 1.f / l0, inv1 = 1.f / l1;
    int g = lane >> 2, t4 = lane & 3;
    size_t rbase = ((size_t)(b * SEQ + qb * BLKS + w * 16 + g)) * Dm + h * DHd;
    #pragma unroll
    for (int nd = 0; nd < 8; nd++) {
        int col = nd * 8 + 2 * t4;
        uint32_t h0, l0w, h1, l1w;
        split2(co[nd][0] * inv0, co[nd][1] * inv0, h0, l0w);
        split2(co[nd][2] * inv1, co[nd][3] * inv1, h1, l1w);
        *(uint32_t*)(ch_g + rbase + col)          = h0;
        *(uint32_t*)(cl_g + rbase + col)          = l0w;
        *(uint32_t*)(ch_g + rbase + 8 * Dm + col) = h1;
        *(uint32_t*)(cl_g + rbase + 8 * Dm + col) = l1w;
    }
}

// ---------------- mean pool + linear head ----------------
__global__ void __launch_bounds__(256) pool1_kernel(
    const float* __restrict__ x, const float* __restrict__ w, float* __restrict__ part)
{
    int b = blockIdx.y, sl = blockIdx.x;
    const float* xb = x + ((size_t)b * SEQ + sl * 128) * Dm;
    __shared__ float ws[Dm];
    for (int i = threadIdx.x; i < Dm; i += 256) ws[i] = w[i];
    __syncthreads();
    float acc = 0.f;
    for (int r = 0; r < 128; r++) {
        const float* xr = xb + (size_t)r * Dm;
        for (int i = threadIdx.x; i < Dm; i += 256) acc += xr[i] * ws[i];
    }
    float t = blk_sum256(acc);
    if (threadIdx.x == 0) part[b * 32 + sl] = t;
}
__global__ void pool2_kernel(const float* __restrict__ part,
                             const float* __restrict__ fb, float* __restrict__ out)
{
    int b = threadIdx.x;
    if (b < BB) {
        float s = 0.f;
        for (int i = 0; i < 32; i++) s += part[b * 32 + i];
        out[b] = s * (1.f / (float)SEQ) + fb[0];
    }
}

// ---------------- driver ----------------
extern "C" void kernel_launch(void* const* d_in, const int* in_sizes, int n_in,
                              void* d_out, int out_size)
{
    const int*   ids     = (const int*)  d_in[0];
    const int*   rb      = (const int*)  d_in[1];
    const float* emb_tok = (const float*)d_in[2];
    const float* emb_pos = (const float*)d_in[3];
    const float* lng     = (const float*)d_in[4];
    const float* lnb     = (const float*)d_in[5];
    const float* Wq = (const float*)d_in[6];  const float* bq = (const float*)d_in[7];
    const float* Wk = (const float*)d_in[8];  const float* bk = (const float*)d_in[9];
    const float* Wv = (const float*)d_in[10]; const float* bv = (const float*)d_in[11];
    const float* Wo = (const float*)d_in[12]; const float* bo = (const float*)d_in[13];
    const float* ln1g = (const float*)d_in[14]; const float* ln1b = (const float*)d_in[15];
    const float* W1 = (const float*)d_in[16]; const float* b1 = (const float*)d_in[17];
    const float* W2 = (const float*)d_in[18]; const float* b2 = (const float*)d_in[19];
    const float* ln2g = (const float*)d_in[20]; const float* ln2b = (const float*)d_in[21];
    const float* fcw = (const float*)d_in[22]; const float* fcb = (const float*)d_in[23];

    float *x, *tmp, *part;
    __nv_bfloat16 *xh, *xl, *qh, *ql, *kh, *kl, *vh, *vl, *ch, *cl, *fh, *fl, *wh, *wl;
    cudaGetSymbolAddress((void**)&x,   g_x);
    cudaGetSymbolAddress((void**)&tmp, g_tmp);
    cudaGetSymbolAddress((void**)&xh,  g_xh);
    cudaGetSymbolAddress((void**)&xl,  g_xl);
    cudaGetSymbolAddress((void**)&qh,  g_qh);
    cudaGetSymbolAddress((void**)&ql,  g_ql);
    cudaGetSymbolAddress((void**)&kh,  g_kh);
    cudaGetSymbolAddress((void**)&kl,  g_kl);
    cudaGetSymbolAddress((void**)&vh,  g_vh);
    cudaGetSymbolAddress((void**)&vl,  g_vl);
    cudaGetSymbolAddress((void**)&ch,  g_ch);
    cudaGetSymbolAddress((void**)&cl,  g_cl);
    cudaGetSymbolAddress((void**)&fh,  g_fh);
    cudaGetSymbolAddress((void**)&fl,  g_fl);
    cudaGetSymbolAddress((void**)&wh,  g_wh);
    cudaGetSymbolAddress((void**)&wl,  g_wl);
    cudaGetSymbolAddress((void**)&part, g_part);

    const int SMEM_GEMM = 2 * STG_B;
    cudaFuncSetAttribute((const void*)gemm_mma<0,1,0>,
                         cudaFuncAttributeMaxDynamicSharedMemorySize, SMEM_GEMM);
    cudaFuncSetAttribute((const void*)gemm_mma<0,0,1>,
                         cudaFuncAttributeMaxDynamicSharedMemorySize, SMEM_GEMM);
    cudaFuncSetAttribute((const void*)gemm_mma<1,0,1>,
                         cudaFuncAttributeMaxDynamicSharedMemorySize, SMEM_GEMM);
    cudaFuncSetAttribute((const void*)attn_mma_kernel,
                         cudaFuncAttributeMaxDynamicSharedMemorySize, A_SMEM);

    dim3 gN(Dm / 128, NTOK / 128);
    dim3 gF(FF / 128, NTOK / 128);
    dim3 gAtt(NB, Hh, BB);
    dim3 gWS(Dm / 32, Dm / 32);

    // launch 0
    embed_ln_kernel<<<NTOK, 256>>>(ids, emb_tok, emb_pos, lng, lnb, x, xh, xl);
    // launches 1..4: layer-0 weight splits (so launch 5 = gemm_mma for ncu)
    {
        wsplit3_kernel<<<dim3(Dm / 32, Dm / 32, 3), 256>>>(Wq, Wk, Wv, wh, wl);
        wsplit_kernel<<<gWS, 256>>>(Wo, wh + 3 * WSZ, wl + 3 * WSZ, Dm, Dm);
        wsplit_kernel<<<dim3(FF / 32, Dm / 32), 256>>>(W1, wh + 4 * (size_t)WSZ, wl + 4 * (size_t)WSZ, Dm, FF);
        wsplit_kernel<<<dim3(Dm / 32, FF / 32), 256>>>(W2, wh + 4 * (size_t)WSZ + W1SZ, wl + 4 * (size_t)WSZ + W1SZ, FF, Dm);
    }
    {
        size_t o = OFFL;
        wsplit3_kernel<<<dim3(Dm / 32, Dm / 32, 3), 256>>>(
            Wq + WSZ, Wk + WSZ, Wv + WSZ, wh + o, wl + o);
        wsplit_kernel<<<gWS, 256>>>(Wo + WSZ, wh + o + 3 * WSZ, wl + o + 3 * WSZ, Dm, Dm);
        wsplit_kernel<<<dim3(FF / 32, Dm / 32), 256>>>(W1 + W1SZ, wh + o + 4 * (size_t)WSZ, wl + o + 4 * (size_t)WSZ, Dm, FF);
        wsplit_kernel<<<dim3(Dm / 32, FF / 32), 256>>>(W2 + W1SZ, wh + o + 4 * (size_t)WSZ + W1SZ, wl + o + 4 * (size_t)WSZ + W1SZ, FF, Dm);
    }
    // wait: layer-1 splits pushed launch index of gemm to 9. Keep layer-0 only upfront
    // (layer-1 splits remain where they are; launch 5 is still the first gemm? No — the
    // two blocks above are launches 1-8.) Accept: first gemm at index 9; ncu -s5 lands
    // on a wsplit3/wsplit — still fine, they're tiny; priority is runtime, not profiling.

    for (int l = 0; l < 2; l++) {
        size_t o = (size_t)l * OFFL;
        gemm_mma<0,0,1><<<gN, 256, SMEM_GEMM>>>(xh, xl, wh + o,           wl + o,           bq + l * Dm, nullptr, qh, ql, NTOK, Dm, Dm);
        gemm_mma<0,0,1><<<gN, 256, SMEM_GEMM>>>(xh, xl, wh + o + WSZ,     wl + o + WSZ,     bk + l * Dm, nullptr, kh, kl, NTOK, Dm, Dm);
        gemm_mma<0,0,1><<<gN, 256, SMEM_GEMM>>>(xh, xl, wh + o + 2 * WSZ, wl + o + 2 * WSZ, bv + l * Dm, nullptr, vh, vl, NTOK, Dm, Dm);
        attn_mma_kernel<<<gAtt, 128, A_SMEM>>>(qh, ql, kh, kl, vh, vl, rb, ch, cl);
        gemm_mma<0,1,0><<<gN, 256, SMEM_GEMM>>>(ch, cl, wh + o + 3 * WSZ, wl + o + 3 * WSZ, bo + l * Dm, tmp, nullptr, nullptr, NTOK, Dm, Dm);
        add_ln_kernel<<<NTOK, 256>>>(x, tmp, ln1g + l * Dm, ln1b + l * Dm, xh, xl);
        gemm_mma<1,0,1><<<gF, 256, SMEM_GEMM>>>(xh, xl, wh + o + 4 * WSZ, wl + o + 4 * WSZ, b1 + l * FF, nullptr, fh, fl, NTOK, FF, Dm);
        gemm_mma<0,1,0><<<gN, 256, SMEM_GEMM>>>(fh, fl, wh + o + 4 * WSZ + W1SZ, wl + o + 4 * WSZ + W1SZ, b2 + l * Dm, tmp, nullptr, nullptr, NTOK, Dm, FF);
        add_ln_kernel<<<NTOK, 256>>>(x, tmp, ln2g + l * Dm, ln2b + l * Dm, xh, xl);
    }

    pool1_kernel<<<dim3(32, BB), 256>>>(x, fcw, part);
    pool2_kernel<<<1, 32>>>(part, fcb, (float*)d_out);
}

// round 7
// speedup vs baseline: 5.5445x; 1.0161x over previous
#include <cuda_runtime.h>
#include <cuda_bf16.h>
#include <math.h>
#include <stdint.h>

// ---------------- problem constants ----------------
#define Dm   768
#define Hh   12
#define DHd  64
#define BLKS 64
#define NB   64
#define SEQ  4096
#define BB   2
#define NTOK (BB*SEQ)
#define RR   3
#define FF   3072
#define QKVD 2304

#define WSZ   589824
#define W1SZ  2359296
#define OFFL  (4*WSZ + 2*W1SZ)

// ---------------- scratch (device globals) ----------------
__device__ float g_x  [NTOK*Dm];
__device__ float g_tmp[NTOK*Dm];
__device__ __nv_bfloat16 g_xh [NTOK*Dm];
__device__ __nv_bfloat16 g_xl [NTOK*Dm];
__device__ __nv_bfloat16 g_qkvh[NTOK*QKVD];
__device__ __nv_bfloat16 g_qkvl[NTOK*QKVD];
__device__ __nv_bfloat16 g_ch [NTOK*Dm];
__device__ __nv_bfloat16 g_cl [NTOK*Dm];
__device__ __nv_bfloat16 g_fh [NTOK*FF];
__device__ __nv_bfloat16 g_fl [NTOK*FF];
__device__ __nv_bfloat16 g_wh [2*OFFL];
__device__ __nv_bfloat16 g_wl [2*OFFL];
__device__ float g_bqkv[QKVD];
__device__ float g_part[64];

// ---------------- helpers ----------------
__device__ __forceinline__ float gelu_tanh(float x) {
    float x3 = x * x * x;
    return 0.5f * x * (1.f + tanhf(0.7978845608028654f * (x + 0.044715f * x3)));
}

__device__ __forceinline__ float blk_sum256(float v) {
    __shared__ float red[32];
    int lane = threadIdx.x & 31, wid = threadIdx.x >> 5;
    #pragma unroll
    for (int o = 16; o > 0; o >>= 1) v += __shfl_xor_sync(0xffffffffu, v, o);
    if (lane == 0) red[wid] = v;
    __syncthreads();
    if (wid == 0) {
        v = (lane < 8) ? red[lane] : 0.f;
        #pragma unroll
        for (int o = 4; o > 0; o >>= 1) v += __shfl_xor_sync(0xffffffffu, v, o);
        if (lane == 0) red[0] = v;
    }
    __syncthreads();
    float r = red[0];
    __syncthreads();
    return r;
}

__device__ __forceinline__ uint32_t s2u(const void* p) {
    uint32_t a;
    asm("{ .reg .u64 t; cvta.to.shared.u64 t, %1; cvt.u32.u64 %0, t; }" : "=r"(a) : "l"(p));
    return a;
}

#define LDSM4(r, a) \
    asm volatile("ldmatrix.sync.aligned.m8n8.x4.shared.b16 {%0,%1,%2,%3}, [%4];" \
        : "=r"((r)[0]), "=r"((r)[1]), "=r"((r)[2]), "=r"((r)[3]) : "r"(a))
#define LDSM2(r0, r1, a) \
    asm volatile("ldmatrix.sync.aligned.m8n8.x2.shared.b16 {%0,%1}, [%2];" \
        : "=r"(r0), "=r"(r1) : "r"(a))
#define LDSM2T(r0, r1, a) \
    asm volatile("ldmatrix.sync.aligned.m8n8.x2.trans.shared.b16 {%0,%1}, [%2];" \
        : "=r"(r0), "=r"(r1) : "r"(a))

#define CPA16(dst, src) \
    asm volatile("cp.async.cg.shared.global [%0], [%1], 16;" :: "r"(dst), "l"(src))
#define CP_COMMIT() asm volatile("cp.async.commit_group;" ::: "memory")
#define CP_WAIT(n)  asm volatile("cp.async.wait_group %0;" :: "n"(n) : "memory")

__device__ __forceinline__ void mma16816(float* c, const uint32_t* a,
                                         uint32_t b0, uint32_t b1) {
    asm volatile(
        "mma.sync.aligned.m16n8k16.row.col.f32.bf16.bf16.f32 "
        "{%0,%1,%2,%3}, {%4,%5,%6,%7}, {%8,%9}, {%0,%1,%2,%3};"
        : "+f"(c[0]), "+f"(c[1]), "+f"(c[2]), "+f"(c[3])
        : "r"(a[0]), "r"(a[1]), "r"(a[2]), "r"(a[3]), "r"(b0), "r"(b1));
}

__device__ __forceinline__ void split2(float a, float b, uint32_t& hi, uint32_t& lo) {
    __nv_bfloat16 ha = __float2bfloat16_rn(a);
    __nv_bfloat16 hb = __float2bfloat16_rn(b);
    __nv_bfloat16 la = __float2bfloat16_rn(a - __bfloat162float(ha));
    __nv_bfloat16 lb = __float2bfloat16_rn(b - __bfloat162float(hb));
    hi = (uint32_t)__bfloat16_as_ushort(ha) | ((uint32_t)__bfloat16_as_ushort(hb) << 16);
    lo = (uint32_t)__bfloat16_as_ushort(la) | ((uint32_t)__bfloat16_as_ushort(lb) << 16);
}

// ---------------- weight transpose + split ----------------
__global__ void __launch_bounds__(256) wsplit_kernel(
    const float* __restrict__ W, __nv_bfloat16* __restrict__ hi,
    __nv_bfloat16* __restrict__ lo, int K, int N)
{
    __shared__ float t[32][33];
    int n0 = blockIdx.x * 32, k0 = blockIdx.y * 32;
    int tx = threadIdx.x & 31, ty = threadIdx.x >> 5;
    #pragma unroll
    for (int j = 0; j < 4; j++)
        t[ty + j * 8][tx] = W[(size_t)(k0 + ty + j * 8) * N + n0 + tx];
    __syncthreads();
    #pragma unroll
    for (int j = 0; j < 4; j++) {
        int n = n0 + ty + j * 8, k = k0 + tx;
        float v = t[tx][ty + j * 8];
        __nv_bfloat16 h = __float2bfloat16_rn(v);
        hi[(size_t)n * K + k] = h;
        lo[(size_t)n * K + k] = __float2bfloat16_rn(v - __bfloat162float(h));
    }
}

__global__ void __launch_bounds__(256) wsplit3_kernel(
    const float* __restrict__ Wa, const float* __restrict__ Wb,
    const float* __restrict__ Wc, __nv_bfloat16* __restrict__ hi,
    __nv_bfloat16* __restrict__ lo)
{
    __shared__ float t[32][33];
    int z = blockIdx.z;
    const float* W = (z == 0) ? Wa : (z == 1) ? Wb : Wc;
    __nv_bfloat16* hz = hi + (size_t)z * WSZ;
    __nv_bfloat16* lz = lo + (size_t)z * WSZ;
    int n0 = blockIdx.x * 32, k0 = blockIdx.y * 32;
    int tx = threadIdx.x & 31, ty = threadIdx.x >> 5;
    #pragma unroll
    for (int j = 0; j < 4; j++)
        t[ty + j * 8][tx] = W[(size_t)(k0 + ty + j * 8) * Dm + n0 + tx];
    __syncthreads();
    #pragma unroll
    for (int j = 0; j < 4; j++) {
        int n = n0 + ty + j * 8, k = k0 + tx;
        float v = t[tx][ty + j * 8];
        __nv_bfloat16 h = __float2bfloat16_rn(v);
        hz[(size_t)n * Dm + k] = h;
        lz[(size_t)n * Dm + k] = __float2bfloat16_rn(v - __bfloat162float(h));
    }
}

__global__ void bias_concat_kernel(const float* __restrict__ a,
    const float* __restrict__ b, const float* __restrict__ c,
    float* __restrict__ o)
{
    int i = blockIdx.x * 256 + threadIdx.x;
    if (i < Dm) { o[i] = a[i]; o[Dm + i] = b[i]; o[2 * Dm + i] = c[i]; }
}

// ---------------- cp.async warp-MMA GEMM ----------------
#define RS_B   80
#define TILE_B (128*RS_B)
#define STG_B  (4*TILE_B)

template<int GELU, int WF32, int WSPL, int KC>
__global__ void __launch_bounds__(256, 2) gemm_mma(
    const __nv_bfloat16* __restrict__ Ahi, const __nv_bfloat16* __restrict__ Alo,
    const __nv_bfloat16* __restrict__ Bhi, const __nv_bfloat16* __restrict__ Blo,
    const float* __restrict__ bias, float* __restrict__ C,
    __nv_bfloat16* __restrict__ Chi, __nv_bfloat16* __restrict__ Clo,
    int M, int N)
{
    const int K = KC * 32;
    extern __shared__ char sm[];
    uint32_t sbase = s2u(sm);
    int tid = threadIdx.x, lane = tid & 31, wid = tid >> 5;
    int m0 = blockIdx.y * 128, n0 = blockIdx.x * 128;
    int wm = (wid & 3) * 32, wn = (wid >> 2) * 64;

    int lr = tid & 127, lh = tid >> 7;
    const __nv_bfloat16* ah_p = Ahi + (size_t)(m0 + lr) * K + lh * 16;
    const __nv_bfloat16* al_p = Alo + (size_t)(m0 + lr) * K + lh * 16;
    const __nv_bfloat16* bh_p = Bhi + (size_t)(n0 + lr) * K + lh * 16;
    const __nv_bfloat16* bl_p = Blo + (size_t)(n0 + lr) * K + lh * 16;
    uint32_t woff = (uint32_t)lr * RS_B + (uint32_t)lh * 32;

    float acc[2][8][4];
    #pragma unroll
    for (int i = 0; i < 2; i++)
        #pragma unroll
        for (int j = 0; j < 8; j++)
            #pragma unroll
            for (int t = 0; t < 4; t++) acc[i][j][t] = 0.f;

    {
        uint32_t d = sbase + woff;
        CPA16(d,                  ah_p);     CPA16(d + 16,              ah_p + 8);
        CPA16(d + TILE_B,         al_p);     CPA16(d + TILE_B + 16,     al_p + 8);
        CPA16(d + 2 * TILE_B,     bh_p);     CPA16(d + 2 * TILE_B + 16, bh_p + 8);
        CPA16(d + 3 * TILE_B,     bl_p);     CPA16(d + 3 * TILE_B + 16, bl_p + 8);
        CP_COMMIT();
    }

    int r16 = lane & 15, c16 = lane >> 4;
    int r8  = lane & 7,  c8  = (lane >> 3) & 1;

    #pragma unroll 2
    for (int c = 0; c < KC; c++) {
        if (c + 1 < KC) {
            uint32_t d = sbase + ((c + 1) & 1) * STG_B + woff;
            int off = (c + 1) * 32;
            CPA16(d,                  ah_p + off);     CPA16(d + 16,              ah_p + off + 8);
            CPA16(d + TILE_B,         al_p + off);     CPA16(d + TILE_B + 16,     al_p + off + 8);
            CPA16(d + 2 * TILE_B,     bh_p + off);     CPA16(d + 2 * TILE_B + 16, bh_p + off + 8);
            CPA16(d + 3 * TILE_B,     bl_p + off);     CPA16(d + 3 * TILE_B + 16, bl_p + off + 8);
            CP_COMMIT();
            CP_WAIT(1);
        } else {
            CP_WAIT(0);
        }
        __syncthreads();
        {
            uint32_t base = sbase + (c & 1) * STG_B;
            #pragma unroll
            for (int ks = 0; ks < 2; ks++) {
                uint32_t ah[2][4], al[2][4];
                #pragma unroll
                for (int mi = 0; mi < 2; mi++) {
                    uint32_t rel = (uint32_t)(wm + mi * 16 + r16) * RS_B
                                 + ks * 32 + c16 * 16;
                    LDSM4(ah[mi], base + rel);
                    LDSM4(al[mi], base + TILE_B + rel);
                }
                #pragma unroll
                for (int ni = 0; ni < 8; ni++) {
                    uint32_t rel = (uint32_t)(wn + ni * 8 + r8) * RS_B
                                 + ks * 32 + c8 * 16;
                    uint32_t bh0, bh1, bl0, bl1;
                    LDSM2(bh0, bh1, base + 2 * TILE_B + rel);
                    LDSM2(bl0, bl1, base + 3 * TILE_B + rel);
                    #pragma unroll
                    for (int mi = 0; mi < 2; mi++) {
                        mma16816(acc[mi][ni], ah[mi], bh0, bh1);
                        mma16816(acc[mi][ni], ah[mi], bl0, bl1);
                        mma16816(acc[mi][ni], al[mi], bh0, bh1);
                    }
                }
            }
        }
        __syncthreads();
    }

    int g = lane >> 2, t4 = lane & 3;
    #pragma unroll
    for (int mi = 0; mi < 2; mi++) {
        int row0 = m0 + wm + mi * 16 + g;
        #pragma unroll
        for (int ni = 0; ni < 8; ni++) {
            int col = n0 + wn + ni * 8 + 2 * t4;
            float2 bi = *(const float2*)(bias + col);
            float2 o0, o1;
            o0.x = acc[mi][ni][0] + bi.x;
            o0.y = acc[mi][ni][1] + bi.y;
            o1.x = acc[mi][ni][2] + bi.x;
            o1.y = acc[mi][ni][3] + bi.y;
            if (GELU) {
                o0.x = gelu_tanh(o0.x); o0.y = gelu_tanh(o0.y);
                o1.x = gelu_tanh(o1.x); o1.y = gelu_tanh(o1.y);
            }
            size_t i0 = (size_t)row0 * N + col;
            size_t i1 = (size_t)(row0 + 8) * N + col;
            if (WF32) {
                *(float2*)(C + i0) = o0;
                *(float2*)(C + i1) = o1;
            }
            if (WSPL) {
                uint32_t h0, l0, h1, l1;
                split2(o0.x, o0.y, h0, l0);
                split2(o1.x, o1.y, h1, l1);
                *(uint32_t*)(Chi + i0) = h0;
                *(uint32_t*)(Clo + i0) = l0;
                *(uint32_t*)(Chi + i1) = h1;
                *(uint32_t*)(Clo + i1) = l1;
            }
        }
    }
}

// ---------------- embedding + LN ----------------
__global__ void __launch_bounds__(256) embed_ln_kernel(
    const int* __restrict__ ids, const float* __restrict__ tok,
    const float* __restrict__ pos, const float* __restrict__ g,
    const float* __restrict__ b, float* __restrict__ x,
    __nv_bfloat16* __restrict__ xh, __nv_bfloat16* __restrict__ xl)
{
    int t = blockIdx.x, s = t & (SEQ - 1), id = ids[t];
    float val[3];
    #pragma unroll
    for (int j = 0; j < 3; j++) {
        int i = threadIdx.x + j * 256;
        val[j] = tok[(size_t)id * Dm + i] + pos[(size_t)s * Dm + i];
    }
    float mean = blk_sum256(val[0] + val[1] + val[2]) * (1.f / 768.f);
    float sq = 0.f;
    #pragma unroll
    for (int j = 0; j < 3; j++) { float d = val[j] - mean; sq += d * d; }
    float rstd = rsqrtf(blk_sum256(sq) * (1.f / 768.f) + 1e-12f);
    #pragma unroll
    for (int j = 0; j < 3; j++) {
        int i = threadIdx.x + j * 256;
        float o = (val[j] - mean) * rstd * g[i] + b[i];
        size_t idx = (size_t)t * Dm + i;
        x[idx] = o;
        __nv_bfloat16 h = __float2bfloat16_rn(o);
        xh[idx] = h;
        xl[idx] = __float2bfloat16_rn(o - __bfloat162float(h));
    }
}

// ---------------- residual add + LN ----------------
__global__ void __launch_bounds__(256) add_ln_kernel(
    float* __restrict__ x, const float* __restrict__ y,
    const float* __restrict__ g, const float* __restrict__ b,
    __nv_bfloat16* __restrict__ xh, __nv_bfloat16* __restrict__ xl)
{
    size_t t = blockIdx.x;
    float* xp = x + t * Dm;
    const float* yp = y + t * Dm;
    float val[3];
    #pragma unroll
    for (int j = 0; j < 3; j++) {
        int i = threadIdx.x + j * 256;
        val[j] = xp[i] + yp[i];
    }
    float mean = blk_sum256(val[0] + val[1] + val[2]) * (1.f / 768.f);
    float sq = 0.f;
    #pragma unroll
    for (int j = 0; j < 3; j++) { float d = val[j] - mean; sq += d * d; }
    float rstd = rsqrtf(blk_sum256(sq) * (1.f / 768.f) + 1e-12f);
    #pragma unroll
    for (int j = 0; j < 3; j++) {
        int i = threadIdx.x + j * 256;
        float o = (val[j] - mean) * rstd * g[i] + b[i];
        xp[i] = o;
        __nv_bfloat16 h = __float2bfloat16_rn(o);
        xh[t * Dm + i] = h;
        xl[t * Dm + i] = __float2bfloat16_rn(o - __bfloat162float(h));
    }
}

// ================= attention =================
#define ARS 144
#define A_QH 0
#define A_QL 9216
#define A_KH 18432
#define A_KL 27648
#define A_VH 36864
#define A_VL 46080
#define A_SMEM 55296
#define D_GRP 36864
#define D_G0  18432
#define D_SMEM (18432 + 2*D_GRP)
#define D_MRG 18432

struct AttnState {
    float m0, m1, l0, l1;
    float co[8][4];
};

// stage K and V hi/lo blocks into smem via cp.async (per-thread slice)
__device__ __forceinline__ void stage_kv(
    const __nv_bfloat16* __restrict__ qkvh, const __nv_bfloat16* __restrict__ qkvl,
    size_t kbase, uint32_t dk, uint32_t dkl, uint32_t dv, uint32_t dvl)
{
    size_t vbase = kbase + Dm;
    CPA16(dk,      qkvh + kbase);      CPA16(dk + 16, qkvh + kbase + 8);
    CPA16(dk + 32, qkvh + kbase + 16); CPA16(dk + 48, qkvh + kbase + 24);
    CPA16(dkl,      qkvl + kbase);      CPA16(dkl + 16, qkvl + kbase + 8);
    CPA16(dkl + 32, qkvl + kbase + 16); CPA16(dkl + 48, qkvl + kbase + 24);
    CPA16(dv,      qkvh + vbase);      CPA16(dv + 16, qkvh + vbase + 8);
    CPA16(dv + 32, qkvh + vbase + 16); CPA16(dv + 48, qkvh + vbase + 24);
    CPA16(dvl,      qkvl + vbase);      CPA16(dvl + 16, qkvl + vbase + 8);
    CPA16(dvl + 32, qkvl + vbase + 16); CPA16(dvl + 48, qkvl + vbase + 24);
    CP_COMMIT(); CP_WAIT(0);
}

__device__ __forceinline__ void attn_block(
    AttnState& st, const uint32_t qfh[4][4], const uint32_t qfl[4][4],
    uint32_t sbase, uint32_t offKH, int lane)
{
    const uint32_t dKL = 9216, dVH = 18432, dVL = 27648; // relative to offKH
    uint32_t kb_h = sbase + offKH + (uint32_t)(lane & 7) * ARS + ((lane >> 3) & 1) * 16;
    float sc[8][4];
    #pragma unroll
    for (int ni = 0; ni < 8; ni++)
        #pragma unroll
        for (int t = 0; t < 4; t++) sc[ni][t] = 0.f;
    #pragma unroll
    for (int ni = 0; ni < 8; ni++) {
        uint32_t ba_h = kb_h + (uint32_t)(ni * 8) * ARS;
        #pragma unroll
        for (int ks = 0; ks < 4; ks++) {
            uint32_t bh0, bh1, bl0, bl1;
            LDSM2(bh0, bh1, ba_h + ks * 32);
            LDSM2(bl0, bl1, ba_h + dKL + ks * 32);
            mma16816(sc[ni], qfh[ks], bh0, bh1);
            mma16816(sc[ni], qfh[ks], bl0, bl1);
            mma16816(sc[ni], qfl[ks], bh0, bh1);
        }
    }
    #pragma unroll
    for (int ni = 0; ni < 8; ni++) {
        sc[ni][0] *= 0.125f; sc[ni][1] *= 0.125f;
        sc[ni][2] *= 0.125f; sc[ni][3] *= 0.125f;
    }
    float bm0 = -1e30f, bm1 = -1e30f;
    #pragma unroll
    for (int ni = 0; ni < 8; ni++) {
        bm0 = fmaxf(bm0, fmaxf(sc[ni][0], sc[ni][1]));
        bm1 = fmaxf(bm1, fmaxf(sc[ni][2], sc[ni][3]));
    }
    bm0 = fmaxf(bm0, __shfl_xor_sync(0xffffffffu, bm0, 1));
    bm0 = fmaxf(bm0, __shfl_xor_sync(0xffffffffu, bm0, 2));
    bm1 = fmaxf(bm1, __shfl_xor_sync(0xffffffffu, bm1, 1));
    bm1 = fmaxf(bm1, __shfl_xor_sync(0xffffffffu, bm1, 2));
    float mn0 = fmaxf(st.m0, bm0), mn1 = fmaxf(st.m1, bm1);
    float corr0 = __expf(st.m0 - mn0), corr1 = __expf(st.m1 - mn1);
    st.m0 = mn0; st.m1 = mn1;
    #pragma unroll
    for (int nd = 0; nd < 8; nd++) {
        st.co[nd][0] *= corr0; st.co[nd][1] *= corr0;
        st.co[nd][2] *= corr1; st.co[nd][3] *= corr1;
    }
    float ls0 = 0.f, ls1 = 0.f;
    #pragma unroll
    for (int ni = 0; ni < 8; ni++) {
        sc[ni][0] = __expf(sc[ni][0] - mn0);
        sc[ni][1] = __expf(sc[ni][1] - mn0);
        sc[ni][2] = __expf(sc[ni][2] - mn1);
        sc[ni][3] = __expf(sc[ni][3] - mn1);
        ls0 += sc[ni][0] + sc[ni][1];
        ls1 += sc[ni][2] + sc[ni][3];
    }
    ls0 += __shfl_xor_sync(0xffffffffu, ls0, 1);
    ls0 += __shfl_xor_sync(0xffffffffu, ls0, 2);
    ls1 += __shfl_xor_sync(0xffffffffu, ls1, 1);
    ls1 += __shfl_xor_sync(0xffffffffu, ls1, 2);
    st.l0 = st.l0 * corr0 + ls0;
    st.l1 = st.l1 * corr1 + ls1;

    uint32_t pah[4][4], pal[4][4];
    #pragma unroll
    for (int ksp = 0; ksp < 4; ksp++) {
        split2(sc[2*ksp][0],   sc[2*ksp][1],   pah[ksp][0], pal[ksp][0]);
        split2(sc[2*ksp][2],   sc[2*ksp][3],   pah[ksp][1], pal[ksp][1]);
        split2(sc[2*ksp+1][0], sc[2*ksp+1][1], pah[ksp][2], pal[ksp][2]);
        split2(sc[2*ksp+1][2], sc[2*ksp+1][3], pah[ksp][3], pal[ksp][3]);
    }
    #pragma unroll
    for (int nd = 0; nd < 8; nd++) {
        #pragma unroll
        for (int ksp = 0; ksp < 4; ksp++) {
            uint32_t va = sbase + offKH + dVH
                        + (uint32_t)(ksp * 16 + (lane & 15)) * ARS + nd * 16;
            uint32_t vh0, vh1, vl0, vl1;
            LDSM2T(vh0, vh1, va);
            LDSM2T(vl0, vl1, va + (dVL - dVH));
            mma16816(st.co[nd], pah[ksp], vh0, vh1);
            mma16816(st.co[nd], pah[ksp], vl0, vl1);
            mma16816(st.co[nd], pal[ksp], vh0, vh1);
        }
    }
}

__device__ __forceinline__ void load_q_frags(
    uint32_t sbase, int warp_q, int lane, uint32_t qfh[4][4], uint32_t qfl[4][4])
{
    uint32_t qa_h = sbase + A_QH + (uint32_t)(warp_q * 16 + (lane & 15)) * ARS + (lane >> 4) * 16;
    uint32_t qa_l = qa_h + (A_QL - A_QH);
    #pragma unroll
    for (int ks = 0; ks < 4; ks++) {
        LDSM4(qfh[ks], qa_h + ks * 32);
        LDSM4(qfl[ks], qa_l + ks * 32);
    }
}

__device__ __forceinline__ void stage_q(
    const __nv_bfloat16* __restrict__ qkvh, const __nv_bfloat16* __restrict__ qkvl,
    uint32_t sbase, int b, int qb, int h, int srow, int shalf)
{
    size_t off = ((size_t)(b * SEQ + qb * BLKS + srow)) * QKVD + h * DHd + shalf * 32;
    uint32_t dh = sbase + A_QH + (uint32_t)srow * ARS + shalf * 64;
    uint32_t dl = sbase + A_QL + (uint32_t)srow * ARS + shalf * 64;
    CPA16(dh,      qkvh + off);      CPA16(dh + 16, qkvh + off + 8);
    CPA16(dh + 32, qkvh + off + 16); CPA16(dh + 48, qkvh + off + 24);
    CPA16(dl,      qkvl + off);      CPA16(dl + 16, qkvl + off + 8);
    CPA16(dl + 32, qkvl + off + 16); CPA16(dl + 48, qkvl + off + 24);
    CP_COMMIT(); CP_WAIT(0);
}

// ---------------- sparse attention (query blocks 1..NB-2) ----------------
__global__ void __launch_bounds__(128) attn_sparse_kernel(
    const __nv_bfloat16* __restrict__ qkvh, const __nv_bfloat16* __restrict__ qkvl,
    const int* __restrict__ rb,
    __nv_bfloat16* __restrict__ ch_g, __nv_bfloat16* __restrict__ cl_g)
{
    extern __shared__ char sb[];
    uint32_t sbase = s2u(sb);
    int b = blockIdx.z, h = blockIdx.y, qb = blockIdx.x + 1;
    int tid = threadIdx.x, lane = tid & 31, w = tid >> 5;
    int srow = tid >> 1, shalf = tid & 1;

    stage_q(qkvh, qkvl, sbase, b, qb, h, srow, shalf);
    __syncthreads();

    uint32_t qfh[4][4], qfl[4][4];
    load_q_frags(sbase, w, lane, qfh, qfl);

    AttnState st;
    st.m0 = st.m1 = -1e30f; st.l0 = st.l1 = 0.f;
    #pragma unroll
    for (int nd = 0; nd < 8; nd++)
        #pragma unroll
        for (int t = 0; t < 4; t++) st.co[nd][t] = 0.f;

    int blist[8];
    blist[0] = 0; blist[1] = qb - 1; blist[2] = qb; blist[3] = qb + 1;
    blist[4] = NB - 1;
    const int* rp = rb + (h * NB + qb) * RR;
    blist[5] = rp[0]; blist[6] = rp[1]; blist[7] = rp[2];

    uint32_t dk  = sbase + A_KH + (uint32_t)srow * ARS + shalf * 64;
    uint32_t dkl = dk + 9216, dv = dk + 18432, dvl = dk + 27648;

    for (int jb = 0; jb < 8; jb++) {
        int kb = blist[jb];
        size_t kbase = ((size_t)(b * SEQ + kb * BLKS + srow)) * QKVD + Dm + h * DHd + shalf * 32;
        __syncthreads();
        stage_kv(qkvh, qkvl, kbase, dk, dkl, dv, dvl);
        __syncthreads();
        attn_block(st, qfh, qfl, sbase, A_KH, lane);
    }

    float inv0 = 1.f / st.l0, inv1 = 1.f / st.l1;
    int g = lane >> 2, t4 = lane & 3;
    size_t rbase = ((size_t)(b * SEQ + qb * BLKS + w * 16 + g)) * Dm + h * DHd;
    #pragma unroll
    for (int nd = 0; nd < 8; nd++) {
        int col = nd * 8 + 2 * t4;
        uint32_t h0, l0w, h1, l1w;
        split2(st.co[nd][0] * inv0, st.co[nd][1] * inv0, h0, l0w);
        split2(st.co[nd][2] * inv1, st.co[nd][3] * inv1, h1, l1w);
        *(uint32_t*)(ch_g + rbase + col)          = h0;
        *(uint32_t*)(cl_g + rbase + col)          = l0w;
        *(uint32_t*)(ch_g + rbase + 8 * Dm + col) = h1;
        *(uint32_t*)(cl_g + rbase + 8 * Dm + col) = l1w;
    }
}

// ---------------- dense attention (query blocks 0, NB-1; 2 warp-groups) ----------------
__global__ void __launch_bounds__(256) attn_dense_kernel(
    const __nv_bfloat16* __restrict__ qkvh, const __nv_bfloat16* __restrict__ qkvl,
    __nv_bfloat16* __restrict__ ch_g, __nv_bfloat16* __restrict__ cl_g)
{
    extern __shared__ char sb[];
    uint32_t sbase = s2u(sb);
    int b = blockIdx.z, h = blockIdx.y;
    int qb = (blockIdx.x == 0) ? 0 : NB - 1;
    int tid = threadIdx.x, lane = tid & 31;
    int grp = tid >> 7, ltid = tid & 127, w = ltid >> 5;
    int srow = ltid >> 1, shalf = ltid & 1;

    if (grp == 0) stage_q(qkvh, qkvl, sbase, b, qb, h, srow, shalf);
    __syncthreads();

    uint32_t qfh[4][4], qfl[4][4];
    load_q_frags(sbase, w, lane, qfh, qfl);

    AttnState st;
    st.m0 = st.m1 = -1e30f; st.l0 = st.l1 = 0.f;
    #pragma unroll
    for (int nd = 0; nd < 8; nd++)
        #pragma unroll
        for (int t = 0; t < 4; t++) st.co[nd][t] = 0.f;

    uint32_t gbase = D_G0 + grp * D_GRP;
    uint32_t dk  = sbase + gbase + (uint32_t)srow * ARS + shalf * 64;
    uint32_t dkl = dk + 9216, dv = dk + 18432, dvl = dk + 27648;

    for (int jb = 0; jb < 32; jb++) {
        int kb = grp * 32 + jb;
        size_t kbase = ((size_t)(b * SEQ + kb * BLKS + srow)) * QKVD + Dm + h * DHd + shalf * 32;
        __syncthreads();
        stage_kv(qkvh, qkvl, kbase, dk, dkl, dv, dvl);
        __syncthreads();
        attn_block(st, qfh, qfl, sbase, gbase, lane);
    }

    // merge group 1 into group 0 via smem (reuse group-0 K area after sync)
    __syncthreads();
    float* mg = (float*)(sb + D_MRG);
    int slot = (w * 32 + lane) * 36;
    if (grp == 1) {
        #pragma unroll
        for (int nd = 0; nd < 8; nd++)
            #pragma unroll
            for (int t = 0; t < 4; t++) mg[slot + nd * 4 + t] = st.co[nd][t];
        mg[slot + 32] = st.m0; mg[slot + 33] = st.m1;
        mg[slot + 34] = st.l0; mg[slot + 35] = st.l1;
    }
    __syncthreads();
    if (grp == 0) {
        float mB0 = mg[slot + 32], mB1 = mg[slot + 33];
        float lB0 = mg[slot + 34], lB1 = mg[slot + 35];
        float M0 = fmaxf(st.m0, mB0), M1 = fmaxf(st.m1, mB1);
        float cA0 = __expf(st.m0 - M0), cB0 = __expf(mB0 - M0);
        float cA1 = __expf(st.m1 - M1), cB1 = __expf(mB1 - M1);
        float L0 = st.l0 * cA0 + lB0 * cB0;
        float L1 = st.l1 * cA1 + lB1 * cB1;
        float inv0 = 1.f / L0, inv1 = 1.f / L1;
        int g = lane >> 2, t4 = lane & 3;
        size_t rbase = ((size_t)(b * SEQ + qb * BLKS + w * 16 + g)) * Dm + h * DHd;
        #pragma unroll
        for (int nd = 0; nd < 8; nd++) {
            float r0 = (st.co[nd][0] * cA0 + mg[slot + nd * 4 + 0] * cB0) * inv0;
            float r1 = (st.co[nd][1] * cA0 + mg[slot + nd * 4 + 1] * cB0) * inv0;
            float r2 = (st.co[nd][2] * cA1 + mg[slot + nd * 4 + 2] * cB1) * inv1;
            float r3 = (st.co[nd][3] * cA1 + mg[slot + nd * 4 + 3] * cB1) * inv1;
            int col = nd * 8 + 2 * t4;
            uint32_t h0, l0w, h1, l1w;
            split2(r0, r1, h0, l0w);
            split2(r2, r3, h1, l1w);
            *(uint32_t*)(ch_g + rbase + col)          = h0;
            *(uint32_t*)(cl_g + rbase + col)          = l0w;
            *(uint32_t*)(ch_g + rbase + 8 * Dm + col) = h1;
            *(uint32_t*)(cl_g + rbase + 8 * Dm + col) = l1w;
        }
    }
}

// ---------------- mean pool + linear head ----------------
__global__ void __launch_bounds__(256) pool1_kernel(
    const float* __restrict__ x, const float* __restrict__ w, float* __restrict__ part)
{
    int b = blockIdx.y, sl = blockIdx.x;
    const float* xb = x + ((size_t)b * SEQ + sl * 128) * Dm;
    __shared__ float ws[Dm];
    for (int i = threadIdx.x; i < Dm; i += 256) ws[i] = w[i];
    __syncthreads();
    float acc = 0.f;
    for (int r = 0; r < 128; r++) {
        const float* xr = xb + (size_t)r * Dm;
        for (int i = threadIdx.x; i < Dm; i += 256) acc += xr[i] * ws[i];
    }
    float t = blk_sum256(acc);
    if (threadIdx.x == 0) part[b * 32 + sl] = t;
}
__global__ void pool2_kernel(const float* __restrict__ part,
                             const float* __restrict__ fb, float* __restrict__ out)
{
    int b = threadIdx.x;
    if (b < BB) {
        float s = 0.f;
        for (int i = 0; i < 32; i++) s += part[b * 32 + i];
        out[b] = s * (1.f / (float)SEQ) + fb[0];
    }
}

// ---------------- driver ----------------
extern "C" void kernel_launch(void* const* d_in, const int* in_sizes, int n_in,
                              void* d_out, int out_size)
{
    const int*   ids     = (const int*)  d_in[0];
    const int*   rb      = (const int*)  d_in[1];
    const float* emb_tok = (const float*)d_in[2];
    const float* emb_pos = (const float*)d_in[3];
    const float* lng     = (const float*)d_in[4];
    const float* lnb     = (const float*)d_in[5];
    const float* Wq = (const float*)d_in[6];  const float* bq = (const float*)d_in[7];
    const float* Wk = (const float*)d_in[8];  const float* bk = (const float*)d_in[9];
    const float* Wv = (const float*)d_in[10]; const float* bv = (const float*)d_in[11];
    const float* Wo = (const float*)d_in[12]; const float* bo = (const float*)d_in[13];
    const float* ln1g = (const float*)d_in[14]; const float* ln1b = (const float*)d_in[15];
    const float* W1 = (const float*)d_in[16]; const float* b1 = (const float*)d_in[17];
    const float* W2 = (const float*)d_in[18]; const float* b2 = (const float*)d_in[19];
    const float* ln2g = (const float*)d_in[20]; const float* ln2b = (const float*)d_in[21];
    const float* fcw = (const float*)d_in[22]; const float* fcb = (const float*)d_in[23];

    float *x, *tmp, *part, *bqkv;
    __nv_bfloat16 *xh, *xl, *qkvh, *qkvl, *ch, *cl, *fh, *fl, *wh, *wl;
    cudaGetSymbolAddress((void**)&x,   g_x);
    cudaGetSymbolAddress((void**)&tmp, g_tmp);
    cudaGetSymbolAddress((void**)&xh,  g_xh);
    cudaGetSymbolAddress((void**)&xl,  g_xl);
    cudaGetSymbolAddress((void**)&qkvh, g_qkvh);
    cudaGetSymbolAddress((void**)&qkvl, g_qkvl);
    cudaGetSymbolAddress((void**)&ch,  g_ch);
    cudaGetSymbolAddress((void**)&cl,  g_cl);
    cudaGetSymbolAddress((void**)&fh,  g_fh);
    cudaGetSymbolAddress((void**)&fl,  g_fl);
    cudaGetSymbolAddress((void**)&wh,  g_wh);
    cudaGetSymbolAddress((void**)&wl,  g_wl);
    cudaGetSymbolAddress((void**)&bqkv, g_bqkv);
    cudaGetSymbolAddress((void**)&part, g_part);

    const int SMEM_GEMM = 2 * STG_B;
    cudaFuncSetAttribute((const void*)gemm_mma<0,0,1,24>,
                         cudaFuncAttributeMaxDynamicSharedMemorySize, SMEM_GEMM);
    cudaFuncSetAttribute((const void*)gemm_mma<0,1,0,24>,
                         cudaFuncAttributeMaxDynamicSharedMemorySize, SMEM_GEMM);
    cudaFuncSetAttribute((const void*)gemm_mma<1,0,1,24>,
                         cudaFuncAttributeMaxDynamicSharedMemorySize, SMEM_GEMM);
    cudaFuncSetAttribute((const void*)gemm_mma<0,1,0,96>,
                         cudaFuncAttributeMaxDynamicSharedMemorySize, SMEM_GEMM);
    cudaFuncSetAttribute((const void*)attn_sparse_kernel,
                         cudaFuncAttributeMaxDynamicSharedMemorySize, A_SMEM);
    cudaFuncSetAttribute((const void*)attn_dense_kernel,
                         cudaFuncAttributeMaxDynamicSharedMemorySize, D_SMEM);

    dim3 gQKV(QKVD / 128, NTOK / 128);
    dim3 gO(Dm / 128, NTOK / 128);
    dim3 gF(FF / 128, NTOK / 128);
    dim3 gAttS(NB - 2, Hh, BB);
    dim3 gAttD(2, Hh, BB);
    dim3 gWS(Dm / 32, Dm / 32);

    embed_ln_kernel<<<NTOK, 256>>>(ids, emb_tok, emb_pos, lng, lnb, x, xh, xl);
    for (int l = 0; l < 2; l++) {
        size_t o = (size_t)l * OFFL;
        wsplit3_kernel<<<dim3(Dm / 32, Dm / 32, 3), 256>>>(
            Wq + (size_t)l * WSZ, Wk + (size_t)l * WSZ, Wv + (size_t)l * WSZ, wh + o, wl + o);
        wsplit_kernel<<<gWS, 256>>>(Wo + (size_t)l * WSZ, wh + o + 3 * WSZ, wl + o + 3 * WSZ, Dm, Dm);
        wsplit_kernel<<<dim3(FF / 32, Dm / 32), 256>>>(W1 + (size_t)l * W1SZ, wh + o + 4 * (size_t)WSZ, wl + o + 4 * (size_t)WSZ, Dm, FF);
        wsplit_kernel<<<dim3(Dm / 32, FF / 32), 256>>>(W2 + (size_t)l * W1SZ, wh + o + 4 * (size_t)WSZ + W1SZ, wl + o + 4 * (size_t)WSZ + W1SZ, FF, Dm);
    }

    for (int l = 0; l < 2; l++) {
        size_t o = (size_t)l * OFFL;
        bias_concat_kernel<<<3, 256>>>(bq + l * Dm, bk + l * Dm, bv + l * Dm, bqkv);
        gemm_mma<0,0,1,24><<<gQKV, 256, SMEM_GEMM>>>(xh, xl, wh + o, wl + o, bqkv,
            nullptr, qkvh, qkvl, NTOK, QKVD);
        attn_sparse_kernel<<<gAttS, 128, A_SMEM>>>(qkvh, qkvl, rb, ch, cl);
        attn_dense_kernel<<<gAttD, 256, D_SMEM>>>(qkvh, qkvl, ch, cl);
        gemm_mma<0,1,0,24><<<gO, 256, SMEM_GEMM>>>(ch, cl, wh + o + 3 * WSZ, wl + o + 3 * WSZ,
            bo + l * Dm, tmp, nullptr, nullptr, NTOK, Dm);
        add_ln_kernel<<<NTOK, 256>>>(x, tmp, ln1g + l * Dm, ln1b + l * Dm, xh, xl);
        gemm_mma<1,0,1,24><<<gF, 256, SMEM_GEMM>>>(xh, xl, wh + o + 4 * WSZ, wl + o + 4 * WSZ,
            b1 + l * FF, nullptr, fh, fl, NTOK, FF);
        gemm_mma<0,1,0,96><<<gO, 256, SMEM_GEMM>>>(fh, fl, wh + o + 4 * WSZ + W1SZ, wl + o + 4 * WSZ + W1SZ,
            b2 + l * Dm, tmp, nullptr, nullptr, NTOK, Dm);
        add_ln_kernel<<<NTOK, 256>>>(x, tmp, ln2g + l * Dm, ln2b + l * Dm, xh, xl);
    }

    pool1_kernel<<<dim3(32, BB), 256>>>(x, fcw, part);
    pool2_kernel<<<1, 32>>>(part, fcb, (float*)d_out);
}